// round 14
// baseline (speedup 1.0000x reference)
#include <cuda_runtime.h>
#include <cuda_fp16.h>
#include <math.h>

// Problem constants
#define B_    2
#define S_    2048
#define C_    1536
#define HQ_   16
#define HKV_  4
#define DQK_  128
#define DV_   96
#define EPS_  1e-5f
#define CLIP_ 5.0f
#define M_    (B_*S_)          // 4096 rows
#define NQKV  2944             // 2048 q + 512 k + 384 v packed columns

// ---------------- scratch (device globals; no allocation) ----------------
__device__ __half g_qkvh[M_ * NQKV];          // packed fp16 QKV GEMM output
__device__ float g_part[2 * M_ * HQ_ * DV_];  // split-kv partial outputs
__device__ float g_psum[2 * M_ * HQ_];        // split-kv partial row sums

// fp16 operands
__device__ __half g_hh[M_ * C_];              // bn1 output
__device__ __half g_wt[NQKV * C_];            // packed Wq|Wk|Wv transposed
__device__ __half g_wo[C_ * C_];              // Wo transposed
__device__ __half g_y[M_ * HQ_ * DV_];        // attention output
__device__ __half g_qh[M_ * HQ_ * DQK_];      // q post-LN/RoPE
__device__ __half g_kh[M_ * HKV_ * DQK_];     // k post-LN/RoPE
__device__ __half g_vh[M_ * HKV_ * DV_];      // v post-LN

// ==================== helpers ====================
__device__ __forceinline__ unsigned smem_u32(const void* p) {
    unsigned a;
    asm("{ .reg .u64 t; cvta.to.shared.u64 t, %1; cvt.u32.u64 %0, t; }" : "=r"(a) : "l"(p));
    return a;
}

#define LDSM4(r0, r1, r2, r3, addr) \
    asm volatile("ldmatrix.sync.aligned.m8n8.x4.shared.b16 {%0,%1,%2,%3}, [%4];" \
        : "=r"(r0), "=r"(r1), "=r"(r2), "=r"(r3) : "r"(addr))

#define LDSM4T(r0, r1, r2, r3, addr) \
    asm volatile("ldmatrix.sync.aligned.m8n8.x4.trans.shared.b16 {%0,%1,%2,%3}, [%4];" \
        : "=r"(r0), "=r"(r1), "=r"(r2), "=r"(r3) : "r"(addr))

#define MMA16816(d, a0, a1, a2, a3, b0, b1) \
    asm volatile("mma.sync.aligned.m16n8k16.row.col.f32.f16.f16.f32 " \
        "{%0,%1,%2,%3}, {%4,%5,%6,%7}, {%8,%9}, {%0,%1,%2,%3};" \
        : "+f"((d)[0]), "+f"((d)[1]), "+f"((d)[2]), "+f"((d)[3]) \
        : "r"(a0), "r"(a1), "r"(a2), "r"(a3), "r"(b0), "r"(b1))

#define CPASYNC16(dst, src) \
    asm volatile("cp.async.cg.shared.global [%0], [%1], 16;" :: "r"(dst), "l"(src))
#define CPASYNC_COMMIT() asm volatile("cp.async.commit_group;" ::: "memory")
#define CPASYNC_WAIT2()  asm volatile("cp.async.wait_group 2;" ::: "memory")
#define CPASYNC_WAIT1()  asm volatile("cp.async.wait_group 1;" ::: "memory")
#define CPASYNC_WAIT0()  asm volatile("cp.async.wait_group 0;" ::: "memory")

__device__ __forceinline__ unsigned pack2h(float p0, float p1) {
    return (unsigned)__half_as_ushort(__float2half_rn(p0)) |
           ((unsigned)__half_as_ushort(__float2half_rn(p1)) << 16);
}
__device__ __forceinline__ float2 unpack2h(unsigned v) {
    float2 r;
    r.x = __half2float(__ushort_as_half((unsigned short)(v & 0xffff)));
    r.y = __half2float(__ushort_as_half((unsigned short)(v >> 16)));
    return r;
}

// ==================== stage 1: bn1 -> single fp16 ====================
__global__ void bn1_kernel(const float* __restrict__ x,
                           const float* __restrict__ g,
                           const float* __restrict__ ms,
                           __half* __restrict__ hh) {
    int i = blockIdx.x * blockDim.x + threadIdx.x;        // float4 index
    int c4 = (i % (C_ / 4)) * 4;
    float4 xv = ((const float4*)x)[i];
    float4 gv = *(const float4*)&g[c4];
    float4 mv = *(const float4*)&ms[c4];
    float o0 = xv.x * rsqrtf(mv.x + EPS_) * gv.x;
    float o1 = xv.y * rsqrtf(mv.y + EPS_) * gv.y;
    float o2 = xv.z * rsqrtf(mv.z + EPS_) * gv.z;
    float o3 = xv.w * rsqrtf(mv.w + EPS_) * gv.w;
    *(unsigned*)&hh[i * 4]     = pack2h(o0, o1);
    *(unsigned*)&hh[i * 4 + 2] = pack2h(o2, o3);
}

// ---------------- weight transpose -> single fp16: W[K,N] -> Wt[N,K] ----------------
__global__ void transpose_h_kernel(const float* __restrict__ W,
                                   __half* __restrict__ Th,
                                   int K, int N) {
    __shared__ float t[32][33];
    int n0 = blockIdx.x * 32, k0 = blockIdx.y * 32;
    int tx = threadIdx.x, ty = threadIdx.y;   // 32 x 8
    #pragma unroll
    for (int i = 0; i < 32; i += 8)
        t[ty + i][tx] = W[(size_t)(k0 + ty + i) * N + n0 + tx];
    __syncthreads();
    #pragma unroll
    for (int i = 0; i < 32; i += 8)
        Th[(size_t)(n0 + ty + i) * K + k0 + tx] = __float2half_rn(t[tx][ty + i]);
}

// ---------------- packed QKV weight transpose -> single fp16 ----------------
__global__ void transpose_qkv_kernel(const float* __restrict__ Wq,
                                     const float* __restrict__ Wk,
                                     const float* __restrict__ Wv,
                                     __half* __restrict__ Th) {
    __shared__ float t[32][33];
    int n0 = blockIdx.x * 32, k0 = blockIdx.y * 32;
    int tx = threadIdx.x, ty = threadIdx.y;   // 32 x 8
    const float* W; int N; int nloc;
    if (n0 < HQ_ * DQK_)                  { W = Wq; N = HQ_ * DQK_;  nloc = n0; }
    else if (n0 < HQ_ * DQK_ + HKV_ * DQK_) { W = Wk; N = HKV_ * DQK_; nloc = n0 - HQ_ * DQK_; }
    else                                   { W = Wv; N = HKV_ * DV_;  nloc = n0 - HQ_ * DQK_ - HKV_ * DQK_; }
    #pragma unroll
    for (int i = 0; i < 32; i += 8)
        t[ty + i][tx] = W[(size_t)(k0 + ty + i) * N + nloc + tx];
    __syncthreads();
    #pragma unroll
    for (int i = 0; i < 32; i += 8)
        Th[(size_t)(n0 + ty + i) * C_ + k0 + tx] = __float2half_rn(t[tx][ty + i]);
}

// ==================== mma.sync fp16 1-term GEMM, 256 threads, 4-stage ====================
template <int BN, bool HOUT>
__global__ __launch_bounds__(256, 1)
void mma_gemm_kernel(const __half* __restrict__ Ah, const __half* __restrict__ Bh,
                     void* __restrict__ Cm, int Mdim, int Ndim, int Kdim,
                     const float* __restrict__ bias,
                     const float* __restrict__ bn_g,
                     const float* __restrict__ bn_ms) {
    constexpr int WMC = (BN == 128) ? 2 : 4;
    constexpr int MSPAN = 128 / WMC;
    constexpr int A_T = MSPAN / 16;
    constexpr unsigned B_BYTES = (unsigned)BN * 128;
    constexpr unsigned SSZ = 16384 + B_BYTES;

    extern __shared__ __align__(1024) char sm[];
    const unsigned sb = smem_u32(sm);
    const int tid = threadIdx.x, wid = tid >> 5, lane = tid & 31;
    const int bm = blockIdx.y * 128, bn = blockIdx.x * BN;
    const int wm = wid % WMC, wn = wid / WMC;

    const __half* srcs[2] = {Ah, Bh};
    const int rowbase[2] = {bm, bn};
    const unsigned offs[2] = {0u, 16384u};
    const int KT = Kdim >> 6;

    auto load_tile_async = [&](int kt, int buf) {
        unsigned base = sb + (unsigned)buf * SSZ;
        #pragma unroll
        for (int p = 0; p < 2; p++) {
            int rows = (p == 0) ? 128 : BN;
            const __half* src = srcs[p] + (size_t)rowbase[p] * Kdim + kt * 64;
            for (int it = 0; it < rows / 32; it++) {
                int chunk = it * 256 + tid;
                int row = chunk >> 3, c = chunk & 7;
                unsigned off = row * 128 + c * 16;
                off ^= (off >> 3) & 0x70;
                CPASYNC16(base + offs[p] + off, (const void*)(src + (size_t)row * Kdim + c * 8));
            }
        }
        CPASYNC_COMMIT();
    };

    float acc[A_T][4][4];
    #pragma unroll
    for (int a = 0; a < A_T; a++)
        #pragma unroll
        for (int n = 0; n < 4; n++)
            #pragma unroll
            for (int q = 0; q < 4; q++) acc[a][n][q] = 0.f;

    const int a_row  = wm * MSPAN + (lane & 15);
    const unsigned a_byte = (lane >> 4) << 4;
    const int b_row  = wn * 32 + (lane & 7) + ((lane >> 4) << 3);
    const unsigned b_byte = ((lane >> 3) & 1) << 4;

    load_tile_async(0, 0);
    load_tile_async(1, 1);
    load_tile_async(2, 2);

    for (int kt = 0; kt < KT; kt++) {
        int b = kt & 3;
        if (kt + 2 < KT)      CPASYNC_WAIT2();
        else if (kt + 1 < KT) CPASYNC_WAIT1();
        else                  CPASYNC_WAIT0();
        __syncthreads();
        if (kt + 3 < KT) load_tile_async(kt + 3, (kt + 3) & 3);

        unsigned baseA = sb + (unsigned)b * SSZ;
        unsigned baseB = baseA + 16384;

        #pragma unroll
        for (int ks = 0; ks < 4; ks++) {
            unsigned bh[8];
            #pragma unroll
            for (int p = 0; p < 2; p++) {
                unsigned off = (unsigned)(b_row + p * 16) * 128 + b_byte + ks * 32;
                off ^= (off >> 3) & 0x70;
                LDSM4(bh[p*4+0], bh[p*4+1], bh[p*4+2], bh[p*4+3], baseB + off);
            }
            #pragma unroll
            for (int a = 0; a < A_T; a++) {
                unsigned offA = (unsigned)(a_row + a * 16) * 128 + a_byte + ks * 32;
                offA ^= (offA >> 3) & 0x70;
                unsigned ah0, ah1, ah2, ah3;
                LDSM4(ah0, ah1, ah2, ah3, baseA + offA);
                #pragma unroll
                for (int nat = 0; nat < 4; nat++) {
                    int p = nat >> 1, q = nat & 1;
                    MMA16816(acc[a][nat], ah0, ah1, ah2, ah3,
                             bh[p*4 + q*2], bh[p*4 + q*2 + 1]);
                }
            }
        }
    }

    #pragma unroll
    for (int a = 0; a < A_T; a++) {
        int r0 = bm + wm * MSPAN + a * 16 + (lane >> 2);
        #pragma unroll
        for (int nat = 0; nat < 4; nat++) {
            int c = bn + wn * 32 + nat * 8 + (lane & 3) * 2;
            float f0 = 1.f, f1 = 1.f, b0 = 0.f, b1 = 0.f;
            if (bias) { b0 = bias[c]; b1 = bias[c + 1]; }
            if (bn_g) {
                f0 = rsqrtf(bn_ms[c] + EPS_) * bn_g[c];
                f1 = rsqrtf(bn_ms[c + 1] + EPS_) * bn_g[c + 1];
            }
            float u0 = (acc[a][nat][0] + b0) * f0;
            float u1 = (acc[a][nat][1] + b1) * f1;
            float u2 = (acc[a][nat][2] + b0) * f0;
            float u3 = (acc[a][nat][3] + b1) * f1;
            if (HOUT) {
                __half* Ch = (__half*)Cm;
                *(unsigned*)&Ch[(size_t)r0 * Ndim + c]       = pack2h(u0, u1);
                *(unsigned*)&Ch[(size_t)(r0 + 8) * Ndim + c] = pack2h(u2, u3);
            } else {
                float* Cf = (float*)Cm;
                float2 v0; v0.x = u0; v0.y = u1;
                float2 v1; v1.x = u2; v1.y = u3;
                *(float2*)&Cf[(size_t)r0 * Ndim + c]       = v0;
                *(float2*)&Cf[(size_t)(r0 + 8) * Ndim + c] = v1;
            }
        }
    }
}

// ---------------- merged LN (+RoPE), fp16 in -> fp16 out ----------------
__global__ void ln_all_kernel(const __half* __restrict__ qkv,
                              const float* __restrict__ qn_g, const float* __restrict__ qn_b,
                              const float* __restrict__ kn_g, const float* __restrict__ kn_b,
                              const float* __restrict__ vn_g, const float* __restrict__ vn_b) {
    int w    = (blockIdx.x * blockDim.x + threadIdx.x) >> 5;
    int lane = threadIdx.x & 31;
    int row  = w / 24, slot = w - row * 24;
    if (row >= M_) return;
    int s = row & (S_ - 1);

    if (slot < 20) {
        bool isq = (slot < 16);
        const __half* p; const float *g, *b; __half* dsth; size_t dst;
        if (isq) {
            p = qkv + (size_t)row * NQKV + slot * 128;
            g = qn_g; b = qn_b; dsth = g_qh;
            dst = ((size_t)row * HQ_ + slot) * 128;
        } else {
            p = qkv + (size_t)row * NQKV + 2048 + (slot - 16) * 128;
            g = kn_g; b = kn_b; dsth = g_kh;
            dst = ((size_t)row * HKV_ + (slot - 16)) * 128;
        }
        float2 v0 = unpack2h(*(const unsigned*)&p[2 * lane]);
        float2 v1 = unpack2h(*(const unsigned*)&p[2 * lane + 64]);

        float sum = v0.x + v0.y + v1.x + v1.y;
        #pragma unroll
        for (int o = 16; o > 0; o >>= 1) sum += __shfl_xor_sync(0xffffffffu, sum, o);
        float mu = sum * (1.f / 128.f);

        float d0 = v0.x - mu, d1 = v0.y - mu, d2 = v1.x - mu, d3 = v1.y - mu;
        float sq = d0 * d0 + d1 * d1 + d2 * d2 + d3 * d3;
        #pragma unroll
        for (int o = 16; o > 0; o >>= 1) sq += __shfl_xor_sync(0xffffffffu, sq, o);
        float inv = rsqrtf(sq * (1.f / 128.f) + EPS_);

        int i0 = 2 * lane, i1 = 2 * lane + 64;
        float a0 = d0 * inv * g[i0]     + b[i0];
        float a1 = d1 * inv * g[i0 + 1] + b[i0 + 1];
        float a2 = d2 * inv * g[i1]     + b[i1];
        float a3 = d3 * inv * g[i1 + 1] + b[i1 + 1];

        const float kl = logf(1985.0f) / 63.0f;
        float f0 = 1.0f / ((float)lane        + expf((float)lane        * kl));
        float f1 = 1.0f / ((float)(lane + 32) + expf((float)(lane + 32) * kl));
        float c0, s0, c1, s1;
        sincosf((float)s * f0, &s0, &c0);
        sincosf((float)s * f1, &s1, &c1);

        float o0 = a0 * c0 - a1 * s0, o1 = a1 * c0 + a0 * s0;
        float o2 = a2 * c1 - a3 * s1, o3 = a3 * c1 + a2 * s1;

        *(unsigned*)&dsth[dst + i0] = pack2h(o0, o1);
        *(unsigned*)&dsth[dst + i1] = pack2h(o2, o3);
    } else {
        const __half* p = qkv + (size_t)row * NQKV + 2560 + (slot - 20) * 96;
        size_t dst = ((size_t)row * HKV_ + (slot - 20)) * 96;
        float x0 = __half2float(p[lane]);
        float x1 = __half2float(p[lane + 32]);
        float x2 = __half2float(p[lane + 64]);
        float sum = x0 + x1 + x2;
        #pragma unroll
        for (int o = 16; o > 0; o >>= 1) sum += __shfl_xor_sync(0xffffffffu, sum, o);
        float mu = sum * (1.f / 96.f);
        float d0 = x0 - mu, d1 = x1 - mu, d2 = x2 - mu;
        float sq = d0 * d0 + d1 * d1 + d2 * d2;
        #pragma unroll
        for (int o = 16; o > 0; o >>= 1) sq += __shfl_xor_sync(0xffffffffu, sq, o);
        float inv = rsqrtf(sq * (1.f / 96.f) + EPS_);
        g_vh[dst + lane]      = __float2half_rn(d0 * inv * vn_g[lane]      + vn_b[lane]);
        g_vh[dst + lane + 32] = __float2half_rn(d1 * inv * vn_g[lane + 32] + vn_b[lane + 32]);
        g_vh[dst + lane + 64] = __float2half_rn(d2 * inv * vn_g[lane + 64] + vn_b[lane + 64]);
    }
}

// ==================== mma.sync fp16 attention (round-11 shape), split-kv x2 ====================
// 8 warps x 16 q rows; softcap interleaved with PV per j-group for MUFU/HMMA overlap.
#define Q_BYTES    32768
#define K_BYTES    16384
#define V_STRIDE   208
#define V_BYTES    (64 * V_STRIDE)
#define KV_BUF     (K_BYTES + V_BYTES)          // 29696
#define ATT_SMEM   (Q_BYTES + 2 * KV_BUF)       // 92160

__global__ __launch_bounds__(256, 1)
void attn_mma_kernel() {
    extern __shared__ __align__(1024) char sm[];
    const unsigned sb = smem_u32(sm);
    const int qb  = blockIdx.x;
    const int h   = blockIdx.y;
    const int bb  = blockIdx.z >> 1;
    const int kvs = blockIdx.z & 1;
    const int hk = h & (HKV_ - 1);
    const int tid = threadIdx.x, wid = tid >> 5, lane = tid & 31;

    {   // Q loads (grouped with kv tile 0)
        #pragma unroll
        for (int it = 0; it < 8; it++) {
            int chunk = it * 256 + tid;
            int row = chunk >> 4, c = chunk & 15;
            unsigned off = row * 256 + c * 16;
            off ^= (off >> 4) & 0x70;
            const __half* src = g_qh +
                ((size_t)(bb * S_ + qb * 128 + row) * HQ_ + h) * DQK_ + c * 8;
            CPASYNC16(sb + off, (const void*)src);
        }
    }

    auto load_kv = [&](int kt, int buf) {
        unsigned base = sb + Q_BYTES + buf * KV_BUF;
        int s0 = (kvs * 16 + kt) * 64;
        #pragma unroll
        for (int it = 0; it < 4; it++) {
            int chunk = it * 256 + tid;
            int row = chunk >> 4, c = chunk & 15;
            unsigned off = row * 256 + c * 16;
            off ^= (off >> 4) & 0x70;
            const __half* src = g_kh +
                ((size_t)(bb * S_ + s0 + row) * HKV_ + hk) * DQK_ + c * 8;
            CPASYNC16(base + off, (const void*)src);
        }
        #pragma unroll
        for (int it = 0; it < 3; it++) {
            int chunk = it * 256 + tid;
            int row = chunk / 12, c = chunk % 12;
            unsigned off = row * V_STRIDE + c * 16;
            const __half* src = g_vh +
                ((size_t)(bb * S_ + s0 + row) * HKV_ + hk) * DV_ + c * 8;
            CPASYNC16(base + K_BYTES + off, (const void*)src);
        }
        CPASYNC_COMMIT();
    };

    load_kv(0, 0);

    float o_[12][4];
    #pragma unroll
    for (int t = 0; t < 12; t++)
        #pragma unroll
        for (int q = 0; q < 4; q++) o_[t][q] = 0.f;
    float rs0 = 0.f, rs1 = 0.f;

    const float scale = 0.08838834764831845f;
    const int a_row  = wid * 16 + (lane & 15);
    const unsigned a_byte = (lane >> 4) << 4;
    const int b_rowc = (lane & 7) + ((lane >> 4) << 3);
    const unsigned b_byte = ((lane >> 3) & 1) << 4;
    const unsigned voff = (unsigned)(lane & 15) * V_STRIDE + ((lane >> 4) << 4);

    const int NT = 16;
    for (int kb = 0; kb < NT; kb++) {
        int b = kb & 1;
        CPASYNC_WAIT0();
        __syncthreads();
        if (kb + 1 < NT) load_kv(kb + 1, b ^ 1);

        unsigned baseK = sb + Q_BYTES + b * KV_BUF;
        unsigned baseV = baseK + K_BYTES;

        float sc[8][4];
        #pragma unroll
        for (int t = 0; t < 8; t++)
            #pragma unroll
            for (int q = 0; q < 4; q++) sc[t][q] = 0.f;

        #pragma unroll
        for (int ks = 0; ks < 8; ks++) {
            unsigned offA = (unsigned)a_row * 256 + a_byte + ks * 32;
            offA ^= (offA >> 4) & 0x70;
            unsigned qh0, qh1, qh2, qh3;
            LDSM4(qh0, qh1, qh2, qh3, sb + offA);
            #pragma unroll
            for (int p = 0; p < 4; p++) {
                unsigned offB = (unsigned)(p * 16 + b_rowc) * 256 + b_byte + ks * 32;
                offB ^= (offB >> 4) & 0x70;
                unsigned kh0, kh1, kh2, kh3;
                LDSM4(kh0, kh1, kh2, kh3, baseK + offB);
                MMA16816(sc[2*p],   qh0, qh1, qh2, qh3, kh0, kh1);
                MMA16816(sc[2*p+1], qh0, qh1, qh2, qh3, kh2, kh3);
            }
        }

        // softcap one j-group (16 rows x 8 keys worth of this thread's 8 logits)
        unsigned ah[4][4];
        auto docap = [&](int j) {
            #pragma unroll
            for (int tt = 0; tt < 2; tt++) {
                int t = 2 * j + tt;
                #pragma unroll
                for (int q = 0; q < 4; q++) {
                    float l = sc[t][q] * scale;
                    float e = __expf(0.4f * l);
                    float th = 1.f - __fdividef(2.f, e + 1.f);
                    float pp = __expf(CLIP_ * th);
                    sc[t][q] = pp;
                    if (q < 2) rs0 += pp; else rs1 += pp;
                }
            }
            ah[j][0] = pack2h(sc[2*j][0],   sc[2*j][1]);
            ah[j][1] = pack2h(sc[2*j][2],   sc[2*j][3]);
            ah[j][2] = pack2h(sc[2*j+1][0], sc[2*j+1][1]);
            ah[j][3] = pack2h(sc[2*j+1][2], sc[2*j+1][3]);
        };

        docap(0);
        #pragma unroll
        for (int j = 0; j < 4; j++) {
            // PV for group j (tensor) — softcap for j+1 (MUFU) issues behind it
            #pragma unroll
            for (int ct = 0; ct < 3; ct++) {
                #pragma unroll
                for (int half = 0; half < 2; half++) {
                    unsigned a0 = voff + j * (16 * V_STRIDE) + ct * 64 + half * 32;
                    unsigned vh0, vh1, vh2, vh3;
                    LDSM4T(vh0, vh1, vh2, vh3, baseV + a0);
                    int nt = ct * 4 + half * 2;
                    MMA16816(o_[nt],   ah[j][0], ah[j][1], ah[j][2], ah[j][3], vh0, vh1);
                    MMA16816(o_[nt+1], ah[j][0], ah[j][1], ah[j][2], ah[j][3], vh2, vh3);
                }
            }
            if (j < 3) docap(j + 1);
        }
    }

    rs0 += __shfl_xor_sync(0xffffffffu, rs0, 1);
    rs0 += __shfl_xor_sync(0xffffffffu, rs0, 2);
    rs1 += __shfl_xor_sync(0xffffffffu, rs1, 1);
    rs1 += __shfl_xor_sync(0xffffffffu, rs1, 2);

    int r0 = qb * 128 + wid * 16 + (lane >> 2);
    size_t base0 = (((size_t)kvs * M_ + bb * S_ + r0) * HQ_ + h) * DV_;
    size_t base1 = base0 + 8 * (size_t)(HQ_ * DV_);
    #pragma unroll
    for (int nt = 0; nt < 12; nt++) {
        int c = nt * 8 + (lane & 3) * 2;
        float2 v0; v0.x = o_[nt][0]; v0.y = o_[nt][1];
        float2 v1; v1.x = o_[nt][2]; v1.y = o_[nt][3];
        *(float2*)&g_part[base0 + c] = v0;
        *(float2*)&g_part[base1 + c] = v1;
    }
    if ((lane & 3) == 0) {
        g_psum[((size_t)kvs * M_ + bb * S_ + r0) * HQ_ + h]       = rs0;
        g_psum[((size_t)kvs * M_ + bb * S_ + r0 + 8) * HQ_ + h]   = rs1;
    }
}

// ---------------- combine split-kv partials -> single fp16 y ----------------
__global__ void attn_combine_kernel() {
    int idx = blockIdx.x * blockDim.x + threadIdx.x;
    int r   = idx / (HQ_ * 24);
    int rem = idx - r * (HQ_ * 24);
    int h   = rem / 24;
    int c4  = (rem - h * 24) * 4;
    size_t o0 = ((size_t)r * HQ_ + h) * DV_ + c4;
    float4 p0 = *(float4*)&g_part[o0];
    float4 p1 = *(float4*)&g_part[(size_t)M_ * HQ_ * DV_ + o0];
    float s = g_psum[(size_t)r * HQ_ + h] + g_psum[(size_t)M_ * HQ_ + (size_t)r * HQ_ + h];
    float inv = 1.0f / s;
    *(unsigned*)&g_y[o0]     = pack2h((p0.x + p1.x) * inv, (p0.y + p1.y) * inv);
    *(unsigned*)&g_y[o0 + 2] = pack2h((p0.z + p1.z) * inv, (p0.w + p1.w) * inv);
}

// ---------------- launch ----------------
extern "C" void kernel_launch(void* const* d_in, const int* in_sizes, int n_in,
                              void* d_out, int out_size) {
    const float* x      = (const float*)d_in[0];
    const float* bn1_g  = (const float*)d_in[1];
    const float* bn1_ms = (const float*)d_in[2];
    const float* Wq     = (const float*)d_in[3];
    const float* Wk     = (const float*)d_in[4];
    const float* Wv     = (const float*)d_in[5];
    const float* qn_g   = (const float*)d_in[6];
    const float* qn_b   = (const float*)d_in[7];
    const float* kn_g   = (const float*)d_in[8];
    const float* kn_b   = (const float*)d_in[9];
    const float* vn_g   = (const float*)d_in[10];
    const float* vn_b   = (const float*)d_in[11];
    const float* Wo     = (const float*)d_in[12];
    const float* bo     = (const float*)d_in[13];
    const float* bn2_g  = (const float*)d_in[14];
    const float* bn2_ms = (const float*)d_in[15];
    float* out = (float*)d_out;

    __half *pqkvh, *phh, *pwt, *pwo, *py;
    cudaGetSymbolAddress((void**)&pqkvh, g_qkvh);
    cudaGetSymbolAddress((void**)&phh, g_hh);
    cudaGetSymbolAddress((void**)&pwt, g_wt);
    cudaGetSymbolAddress((void**)&pwo, g_wo);
    cudaGetSymbolAddress((void**)&py, g_y);

    cudaFuncSetAttribute((const void*)mma_gemm_kernel<128, true>,
                         cudaFuncAttributeMaxDynamicSharedMemorySize, 4 * 32768);
    cudaFuncSetAttribute((const void*)mma_gemm_kernel<64, false>,
                         cudaFuncAttributeMaxDynamicSharedMemorySize, 4 * 24576);
    cudaFuncSetAttribute(attn_mma_kernel, cudaFuncAttributeMaxDynamicSharedMemorySize, ATT_SMEM);

    // 1. rms_bn1 -> fp16
    bn1_kernel<<<(M_ * C_ / 4) / 256, 256>>>(x, bn1_g, bn1_ms, phh);
    // 2. Wo transpose
    transpose_h_kernel<<<dim3(C_/32, C_/32), dim3(32,8)>>>(Wo, pwo, C_, C_);
    // 3. packed QKV weight transpose
    transpose_qkv_kernel<<<dim3(NQKV/32, C_/32), dim3(32,8)>>>(Wq, Wk, Wv, pwt);
    // 4. merged QKV projection, 256 threads, fp16 out (profiled launch)
    mma_gemm_kernel<128, true><<<dim3(NQKV/128, M_/128), 256, 4 * 32768>>>(
        phh, pwt, pqkvh, M_, NQKV, C_, nullptr, nullptr, nullptr);
    // 5. merged LN (+RoPE), fp16 in
    ln_all_kernel<<<(M_ * 24) / 8, 256>>>(pqkvh, qn_g, qn_b, kn_g, kn_b, vn_g, vn_b);
    // 6. attention, split-kv x2
    attn_mma_kernel<<<dim3(S_ / 128, HQ_, B_ * 2), 256, ATT_SMEM>>>();
    // 7. combine partials -> y fp16
    attn_combine_kernel<<<(M_ * HQ_ * 24) / 256, 256>>>();
    // 8. out projection + bias + rms_bn2 -> d_out
    mma_gemm_kernel<64, false><<<dim3(C_/64, M_/128), 256, 4 * 24576>>>(
        py, pwo, out, M_, C_, HQ_*DV_, bo, bn2_g, bn2_ms);
}

// round 15
// speedup vs baseline: 1.5143x; 1.5143x over previous
#include <cuda_runtime.h>
#include <cuda_fp16.h>
#include <math.h>

// Problem constants
#define B_    2
#define S_    2048
#define C_    1536
#define HQ_   16
#define HKV_  4
#define DQK_  128
#define DV_   96
#define EPS_  1e-5f
#define CLIP_ 5.0f
#define M_    (B_*S_)          // 4096 rows
#define NQKV  2944             // 2048 q + 512 k + 384 v packed columns

// ---------------- scratch (device globals; no allocation) ----------------
__device__ __half g_qkvh[M_ * NQKV];          // packed fp16 QKV GEMM output
__device__ float g_part[2 * M_ * HQ_ * DV_];  // split-kv partial outputs
__device__ float g_psum[2 * M_ * HQ_];        // split-kv partial row sums

// fp16 operands
__device__ __half g_hh[M_ * C_];              // bn1 output
__device__ __half g_wt[NQKV * C_];            // packed Wq|Wk|Wv transposed
__device__ __half g_wo[C_ * C_];              // Wo transposed
__device__ __half g_y[M_ * HQ_ * DV_];        // attention output
__device__ __half g_qh[M_ * HQ_ * DQK_];      // q post-LN/RoPE
__device__ __half g_kh[M_ * HKV_ * DQK_];     // k post-LN/RoPE
__device__ __half g_vh[M_ * HKV_ * DV_];      // v post-LN

// ==================== helpers ====================
__device__ __forceinline__ unsigned smem_u32(const void* p) {
    unsigned a;
    asm("{ .reg .u64 t; cvta.to.shared.u64 t, %1; cvt.u32.u64 %0, t; }" : "=r"(a) : "l"(p));
    return a;
}

#define LDSM4(r0, r1, r2, r3, addr) \
    asm volatile("ldmatrix.sync.aligned.m8n8.x4.shared.b16 {%0,%1,%2,%3}, [%4];" \
        : "=r"(r0), "=r"(r1), "=r"(r2), "=r"(r3) : "r"(addr))

#define LDSM4T(r0, r1, r2, r3, addr) \
    asm volatile("ldmatrix.sync.aligned.m8n8.x4.trans.shared.b16 {%0,%1,%2,%3}, [%4];" \
        : "=r"(r0), "=r"(r1), "=r"(r2), "=r"(r3) : "r"(addr))

#define MMA16816(d, a0, a1, a2, a3, b0, b1) \
    asm volatile("mma.sync.aligned.m16n8k16.row.col.f32.f16.f16.f32 " \
        "{%0,%1,%2,%3}, {%4,%5,%6,%7}, {%8,%9}, {%0,%1,%2,%3};" \
        : "+f"((d)[0]), "+f"((d)[1]), "+f"((d)[2]), "+f"((d)[3]) \
        : "r"(a0), "r"(a1), "r"(a2), "r"(a3), "r"(b0), "r"(b1))

#define CPASYNC16(dst, src) \
    asm volatile("cp.async.cg.shared.global [%0], [%1], 16;" :: "r"(dst), "l"(src))
#define CPASYNC_COMMIT() asm volatile("cp.async.commit_group;" ::: "memory")
#define CPASYNC_WAIT2()  asm volatile("cp.async.wait_group 2;" ::: "memory")
#define CPASYNC_WAIT1()  asm volatile("cp.async.wait_group 1;" ::: "memory")
#define CPASYNC_WAIT0()  asm volatile("cp.async.wait_group 0;" ::: "memory")

__device__ __forceinline__ unsigned pack2h(float p0, float p1) {
    return (unsigned)__half_as_ushort(__float2half_rn(p0)) |
           ((unsigned)__half_as_ushort(__float2half_rn(p1)) << 16);
}
__device__ __forceinline__ float2 unpack2h(unsigned v) {
    float2 r;
    r.x = __half2float(__ushort_as_half((unsigned short)(v & 0xffff)));
    r.y = __half2float(__ushort_as_half((unsigned short)(v >> 16)));
    return r;
}

// ==================== stage 1: bn1 -> single fp16 ====================
__global__ void bn1_kernel(const float* __restrict__ x,
                           const float* __restrict__ g,
                           const float* __restrict__ ms,
                           __half* __restrict__ hh) {
    int i = blockIdx.x * blockDim.x + threadIdx.x;        // float4 index
    int c4 = (i % (C_ / 4)) * 4;
    float4 xv = ((const float4*)x)[i];
    float4 gv = *(const float4*)&g[c4];
    float4 mv = *(const float4*)&ms[c4];
    float o0 = xv.x * rsqrtf(mv.x + EPS_) * gv.x;
    float o1 = xv.y * rsqrtf(mv.y + EPS_) * gv.y;
    float o2 = xv.z * rsqrtf(mv.z + EPS_) * gv.z;
    float o3 = xv.w * rsqrtf(mv.w + EPS_) * gv.w;
    *(unsigned*)&hh[i * 4]     = pack2h(o0, o1);
    *(unsigned*)&hh[i * 4 + 2] = pack2h(o2, o3);
}

// ---------------- weight transpose -> single fp16: W[K,N] -> Wt[N,K] ----------------
__global__ void transpose_h_kernel(const float* __restrict__ W,
                                   __half* __restrict__ Th,
                                   int K, int N) {
    __shared__ float t[32][33];
    int n0 = blockIdx.x * 32, k0 = blockIdx.y * 32;
    int tx = threadIdx.x, ty = threadIdx.y;   // 32 x 8
    #pragma unroll
    for (int i = 0; i < 32; i += 8)
        t[ty + i][tx] = W[(size_t)(k0 + ty + i) * N + n0 + tx];
    __syncthreads();
    #pragma unroll
    for (int i = 0; i < 32; i += 8)
        Th[(size_t)(n0 + ty + i) * K + k0 + tx] = __float2half_rn(t[tx][ty + i]);
}

// ---------------- packed QKV weight transpose -> single fp16 ----------------
__global__ void transpose_qkv_kernel(const float* __restrict__ Wq,
                                     const float* __restrict__ Wk,
                                     const float* __restrict__ Wv,
                                     __half* __restrict__ Th) {
    __shared__ float t[32][33];
    int n0 = blockIdx.x * 32, k0 = blockIdx.y * 32;
    int tx = threadIdx.x, ty = threadIdx.y;   // 32 x 8
    const float* W; int N; int nloc;
    if (n0 < HQ_ * DQK_)                  { W = Wq; N = HQ_ * DQK_;  nloc = n0; }
    else if (n0 < HQ_ * DQK_ + HKV_ * DQK_) { W = Wk; N = HKV_ * DQK_; nloc = n0 - HQ_ * DQK_; }
    else                                   { W = Wv; N = HKV_ * DV_;  nloc = n0 - HQ_ * DQK_ - HKV_ * DQK_; }
    #pragma unroll
    for (int i = 0; i < 32; i += 8)
        t[ty + i][tx] = W[(size_t)(k0 + ty + i) * N + nloc + tx];
    __syncthreads();
    #pragma unroll
    for (int i = 0; i < 32; i += 8)
        Th[(size_t)(n0 + ty + i) * C_ + k0 + tx] = __float2half_rn(t[tx][ty + i]);
}

// ==================== mma.sync fp16 1-term GEMM, 256 threads, 4-stage ====================
template <int BN, bool HOUT>
__global__ __launch_bounds__(256, 1)
void mma_gemm_kernel(const __half* __restrict__ Ah, const __half* __restrict__ Bh,
                     void* __restrict__ Cm, int Mdim, int Ndim, int Kdim,
                     const float* __restrict__ bias,
                     const float* __restrict__ bn_g,
                     const float* __restrict__ bn_ms) {
    constexpr int WMC = (BN == 128) ? 2 : 4;
    constexpr int MSPAN = 128 / WMC;
    constexpr int A_T = MSPAN / 16;
    constexpr unsigned B_BYTES = (unsigned)BN * 128;
    constexpr unsigned SSZ = 16384 + B_BYTES;

    extern __shared__ __align__(1024) char sm[];
    const unsigned sb = smem_u32(sm);
    const int tid = threadIdx.x, wid = tid >> 5, lane = tid & 31;
    const int bm = blockIdx.y * 128, bn = blockIdx.x * BN;
    const int wm = wid % WMC, wn = wid / WMC;

    const __half* srcs[2] = {Ah, Bh};
    const int rowbase[2] = {bm, bn};
    const unsigned offs[2] = {0u, 16384u};
    const int KT = Kdim >> 6;

    auto load_tile_async = [&](int kt, int buf) {
        unsigned base = sb + (unsigned)buf * SSZ;
        #pragma unroll
        for (int p = 0; p < 2; p++) {
            int rows = (p == 0) ? 128 : BN;
            const __half* src = srcs[p] + (size_t)rowbase[p] * Kdim + kt * 64;
            for (int it = 0; it < rows / 32; it++) {
                int chunk = it * 256 + tid;
                int row = chunk >> 3, c = chunk & 7;
                unsigned off = row * 128 + c * 16;
                off ^= (off >> 3) & 0x70;
                CPASYNC16(base + offs[p] + off, (const void*)(src + (size_t)row * Kdim + c * 8));
            }
        }
        CPASYNC_COMMIT();
    };

    float acc[A_T][4][4];
    #pragma unroll
    for (int a = 0; a < A_T; a++)
        #pragma unroll
        for (int n = 0; n < 4; n++)
            #pragma unroll
            for (int q = 0; q < 4; q++) acc[a][n][q] = 0.f;

    const int a_row  = wm * MSPAN + (lane & 15);
    const unsigned a_byte = (lane >> 4) << 4;
    const int b_row  = wn * 32 + (lane & 7) + ((lane >> 4) << 3);
    const unsigned b_byte = ((lane >> 3) & 1) << 4;

    load_tile_async(0, 0);
    load_tile_async(1, 1);
    load_tile_async(2, 2);

    for (int kt = 0; kt < KT; kt++) {
        int b = kt & 3;
        if (kt + 2 < KT)      CPASYNC_WAIT2();
        else if (kt + 1 < KT) CPASYNC_WAIT1();
        else                  CPASYNC_WAIT0();
        __syncthreads();
        if (kt + 3 < KT) load_tile_async(kt + 3, (kt + 3) & 3);

        unsigned baseA = sb + (unsigned)b * SSZ;
        unsigned baseB = baseA + 16384;

        #pragma unroll
        for (int ks = 0; ks < 4; ks++) {
            unsigned bh[8];
            #pragma unroll
            for (int p = 0; p < 2; p++) {
                unsigned off = (unsigned)(b_row + p * 16) * 128 + b_byte + ks * 32;
                off ^= (off >> 3) & 0x70;
                LDSM4(bh[p*4+0], bh[p*4+1], bh[p*4+2], bh[p*4+3], baseB + off);
            }
            #pragma unroll
            for (int a = 0; a < A_T; a++) {
                unsigned offA = (unsigned)(a_row + a * 16) * 128 + a_byte + ks * 32;
                offA ^= (offA >> 3) & 0x70;
                unsigned ah0, ah1, ah2, ah3;
                LDSM4(ah0, ah1, ah2, ah3, baseA + offA);
                #pragma unroll
                for (int nat = 0; nat < 4; nat++) {
                    int p = nat >> 1, q = nat & 1;
                    MMA16816(acc[a][nat], ah0, ah1, ah2, ah3,
                             bh[p*4 + q*2], bh[p*4 + q*2 + 1]);
                }
            }
        }
    }

    #pragma unroll
    for (int a = 0; a < A_T; a++) {
        int r0 = bm + wm * MSPAN + a * 16 + (lane >> 2);
        #pragma unroll
        for (int nat = 0; nat < 4; nat++) {
            int c = bn + wn * 32 + nat * 8 + (lane & 3) * 2;
            float f0 = 1.f, f1 = 1.f, b0 = 0.f, b1 = 0.f;
            if (bias) { b0 = bias[c]; b1 = bias[c + 1]; }
            if (bn_g) {
                f0 = rsqrtf(bn_ms[c] + EPS_) * bn_g[c];
                f1 = rsqrtf(bn_ms[c + 1] + EPS_) * bn_g[c + 1];
            }
            float u0 = (acc[a][nat][0] + b0) * f0;
            float u1 = (acc[a][nat][1] + b1) * f1;
            float u2 = (acc[a][nat][2] + b0) * f0;
            float u3 = (acc[a][nat][3] + b1) * f1;
            if (HOUT) {
                __half* Ch = (__half*)Cm;
                *(unsigned*)&Ch[(size_t)r0 * Ndim + c]       = pack2h(u0, u1);
                *(unsigned*)&Ch[(size_t)(r0 + 8) * Ndim + c] = pack2h(u2, u3);
            } else {
                float* Cf = (float*)Cm;
                float2 v0; v0.x = u0; v0.y = u1;
                float2 v1; v1.x = u2; v1.y = u3;
                *(float2*)&Cf[(size_t)r0 * Ndim + c]       = v0;
                *(float2*)&Cf[(size_t)(r0 + 8) * Ndim + c] = v1;
            }
        }
    }
}

// ---------------- merged LN (+RoPE), fp16 in -> fp16 out ----------------
__global__ void ln_all_kernel(const __half* __restrict__ qkv,
                              const float* __restrict__ qn_g, const float* __restrict__ qn_b,
                              const float* __restrict__ kn_g, const float* __restrict__ kn_b,
                              const float* __restrict__ vn_g, const float* __restrict__ vn_b) {
    int w    = (blockIdx.x * blockDim.x + threadIdx.x) >> 5;
    int lane = threadIdx.x & 31;
    int row  = w / 24, slot = w - row * 24;
    if (row >= M_) return;
    int s = row & (S_ - 1);

    if (slot < 20) {
        bool isq = (slot < 16);
        const __half* p; const float *g, *b; __half* dsth; size_t dst;
        if (isq) {
            p = qkv + (size_t)row * NQKV + slot * 128;
            g = qn_g; b = qn_b; dsth = g_qh;
            dst = ((size_t)row * HQ_ + slot) * 128;
        } else {
            p = qkv + (size_t)row * NQKV + 2048 + (slot - 16) * 128;
            g = kn_g; b = kn_b; dsth = g_kh;
            dst = ((size_t)row * HKV_ + (slot - 16)) * 128;
        }
        float2 v0 = unpack2h(*(const unsigned*)&p[2 * lane]);
        float2 v1 = unpack2h(*(const unsigned*)&p[2 * lane + 64]);

        float sum = v0.x + v0.y + v1.x + v1.y;
        #pragma unroll
        for (int o = 16; o > 0; o >>= 1) sum += __shfl_xor_sync(0xffffffffu, sum, o);
        float mu = sum * (1.f / 128.f);

        float d0 = v0.x - mu, d1 = v0.y - mu, d2 = v1.x - mu, d3 = v1.y - mu;
        float sq = d0 * d0 + d1 * d1 + d2 * d2 + d3 * d3;
        #pragma unroll
        for (int o = 16; o > 0; o >>= 1) sq += __shfl_xor_sync(0xffffffffu, sq, o);
        float inv = rsqrtf(sq * (1.f / 128.f) + EPS_);

        int i0 = 2 * lane, i1 = 2 * lane + 64;
        float a0 = d0 * inv * g[i0]     + b[i0];
        float a1 = d1 * inv * g[i0 + 1] + b[i0 + 1];
        float a2 = d2 * inv * g[i1]     + b[i1];
        float a3 = d3 * inv * g[i1 + 1] + b[i1 + 1];

        const float kl = logf(1985.0f) / 63.0f;
        float f0 = 1.0f / ((float)lane        + expf((float)lane        * kl));
        float f1 = 1.0f / ((float)(lane + 32) + expf((float)(lane + 32) * kl));
        float c0, s0, c1, s1;
        sincosf((float)s * f0, &s0, &c0);
        sincosf((float)s * f1, &s1, &c1);

        float o0 = a0 * c0 - a1 * s0, o1 = a1 * c0 + a0 * s0;
        float o2 = a2 * c1 - a3 * s1, o3 = a3 * c1 + a2 * s1;

        *(unsigned*)&dsth[dst + i0] = pack2h(o0, o1);
        *(unsigned*)&dsth[dst + i1] = pack2h(o2, o3);
    } else {
        const __half* p = qkv + (size_t)row * NQKV + 2560 + (slot - 20) * 96;
        size_t dst = ((size_t)row * HKV_ + (slot - 20)) * 96;
        float x0 = __half2float(p[lane]);
        float x1 = __half2float(p[lane + 32]);
        float x2 = __half2float(p[lane + 64]);
        float sum = x0 + x1 + x2;
        #pragma unroll
        for (int o = 16; o > 0; o >>= 1) sum += __shfl_xor_sync(0xffffffffu, sum, o);
        float mu = sum * (1.f / 96.f);
        float d0 = x0 - mu, d1 = x1 - mu, d2 = x2 - mu;
        float sq = d0 * d0 + d1 * d1 + d2 * d2;
        #pragma unroll
        for (int o = 16; o > 0; o >>= 1) sq += __shfl_xor_sync(0xffffffffu, sq, o);
        float inv = rsqrtf(sq * (1.f / 96.f) + EPS_);
        g_vh[dst + lane]      = __float2half_rn(d0 * inv * vn_g[lane]      + vn_b[lane]);
        g_vh[dst + lane + 32] = __float2half_rn(d1 * inv * vn_g[lane + 32] + vn_b[lane + 32]);
        g_vh[dst + lane + 64] = __float2half_rn(d2 * inv * vn_g[lane + 64] + vn_b[lane + 64]);
    }
}

// ==================== mma.sync fp16 attention (round-11 body), split-kv x2 ====================
#define Q_BYTES    32768
#define K_BYTES    16384
#define V_STRIDE   208
#define V_BYTES    (64 * V_STRIDE)
#define KV_BUF     (K_BYTES + V_BYTES)          // 29696
#define ATT_SMEM   (Q_BYTES + 2 * KV_BUF)       // 92160

__global__ __launch_bounds__(256, 1)
void attn_mma_kernel() {
    extern __shared__ __align__(1024) char sm[];
    const unsigned sb = smem_u32(sm);
    const int qb  = blockIdx.x;
    const int h   = blockIdx.y;
    const int bb  = blockIdx.z >> 1;
    const int kvs = blockIdx.z & 1;
    const int hk = h & (HKV_ - 1);
    const int tid = threadIdx.x, wid = tid >> 5, lane = tid & 31;

    {   // Q loads (grouped with kv tile 0)
        #pragma unroll
        for (int it = 0; it < 8; it++) {
            int chunk = it * 256 + tid;
            int row = chunk >> 4, c = chunk & 15;
            unsigned off = row * 256 + c * 16;
            off ^= (off >> 4) & 0x70;
            const __half* src = g_qh +
                ((size_t)(bb * S_ + qb * 128 + row) * HQ_ + h) * DQK_ + c * 8;
            CPASYNC16(sb + off, (const void*)src);
        }
    }

    auto load_kv = [&](int kt, int buf) {
        unsigned base = sb + Q_BYTES + buf * KV_BUF;
        int s0 = (kvs * 16 + kt) * 64;
        #pragma unroll
        for (int it = 0; it < 4; it++) {
            int chunk = it * 256 + tid;
            int row = chunk >> 4, c = chunk & 15;
            unsigned off = row * 256 + c * 16;
            off ^= (off >> 4) & 0x70;
            const __half* src = g_kh +
                ((size_t)(bb * S_ + s0 + row) * HKV_ + hk) * DQK_ + c * 8;
            CPASYNC16(base + off, (const void*)src);
        }
        #pragma unroll
        for (int it = 0; it < 3; it++) {
            int chunk = it * 256 + tid;
            int row = chunk / 12, c = chunk % 12;
            unsigned off = row * V_STRIDE + c * 16;
            const __half* src = g_vh +
                ((size_t)(bb * S_ + s0 + row) * HKV_ + hk) * DV_ + c * 8;
            CPASYNC16(base + K_BYTES + off, (const void*)src);
        }
        CPASYNC_COMMIT();
    };

    load_kv(0, 0);

    float o_[12][4];
    #pragma unroll
    for (int t = 0; t < 12; t++)
        #pragma unroll
        for (int q = 0; q < 4; q++) o_[t][q] = 0.f;
    float rs0 = 0.f, rs1 = 0.f;

    const float scale = 0.08838834764831845f;
    const int a_row  = wid * 16 + (lane & 15);
    const unsigned a_byte = (lane >> 4) << 4;
    const int b_rowc = (lane & 7) + ((lane >> 4) << 3);
    const unsigned b_byte = ((lane >> 3) & 1) << 4;

    const int NT = 16;
    for (int kb = 0; kb < NT; kb++) {
        int b = kb & 1;
        CPASYNC_WAIT0();
        __syncthreads();
        if (kb + 1 < NT) load_kv(kb + 1, b ^ 1);

        unsigned baseK = sb + Q_BYTES + b * KV_BUF;
        unsigned baseV = baseK + K_BYTES;

        float sc[8][4];
        #pragma unroll
        for (int t = 0; t < 8; t++)
            #pragma unroll
            for (int q = 0; q < 4; q++) sc[t][q] = 0.f;

        #pragma unroll
        for (int ks = 0; ks < 8; ks++) {
            unsigned offA = (unsigned)a_row * 256 + a_byte + ks * 32;
            offA ^= (offA >> 4) & 0x70;
            unsigned qh0, qh1, qh2, qh3;
            LDSM4(qh0, qh1, qh2, qh3, sb + offA);
            #pragma unroll
            for (int p = 0; p < 4; p++) {
                unsigned offB = (unsigned)(p * 16 + b_rowc) * 256 + b_byte + ks * 32;
                offB ^= (offB >> 4) & 0x70;
                unsigned kh0, kh1, kh2, kh3;
                LDSM4(kh0, kh1, kh2, kh3, baseK + offB);
                MMA16816(sc[2*p],   qh0, qh1, qh2, qh3, kh0, kh1);
                MMA16816(sc[2*p+1], qh0, qh1, qh2, qh3, kh2, kh3);
            }
        }

        #pragma unroll
        for (int t = 0; t < 8; t++) {
            #pragma unroll
            for (int q = 0; q < 4; q++) {
                float l = sc[t][q] * scale;
                float e = __expf(0.4f * l);
                float th = 1.f - __fdividef(2.f, e + 1.f);
                float pp = __expf(CLIP_ * th);
                sc[t][q] = pp;
                if (q < 2) rs0 += pp; else rs1 += pp;
            }
        }

        unsigned ah[4][4];
        #pragma unroll
        for (int j = 0; j < 4; j++) {
            ah[j][0] = pack2h(sc[2*j][0],   sc[2*j][1]);
            ah[j][1] = pack2h(sc[2*j][2],   sc[2*j][3]);
            ah[j][2] = pack2h(sc[2*j+1][0], sc[2*j+1][1]);
            ah[j][3] = pack2h(sc[2*j+1][2], sc[2*j+1][3]);
        }

        unsigned voff = (unsigned)(lane & 15) * V_STRIDE + ((lane >> 4) << 4);
        #pragma unroll
        for (int ct = 0; ct < 3; ct++) {
            #pragma unroll
            for (int half = 0; half < 2; half++) {
                #pragma unroll
                for (int j = 0; j < 4; j++) {
                    unsigned a0 = voff + j * (16 * V_STRIDE) + ct * 64 + half * 32;
                    unsigned vh0, vh1, vh2, vh3;
                    LDSM4T(vh0, vh1, vh2, vh3, baseV + a0);
                    int nt = ct * 4 + half * 2;
                    MMA16816(o_[nt],   ah[j][0], ah[j][1], ah[j][2], ah[j][3], vh0, vh1);
                    MMA16816(o_[nt+1], ah[j][0], ah[j][1], ah[j][2], ah[j][3], vh2, vh3);
                }
            }
        }
    }

    rs0 += __shfl_xor_sync(0xffffffffu, rs0, 1);
    rs0 += __shfl_xor_sync(0xffffffffu, rs0, 2);
    rs1 += __shfl_xor_sync(0xffffffffu, rs1, 1);
    rs1 += __shfl_xor_sync(0xffffffffu, rs1, 2);

    int r0 = qb * 128 + wid * 16 + (lane >> 2);
    size_t base0 = (((size_t)kvs * M_ + bb * S_ + r0) * HQ_ + h) * DV_;
    size_t base1 = base0 + 8 * (size_t)(HQ_ * DV_);
    #pragma unroll
    for (int nt = 0; nt < 12; nt++) {
        int c = nt * 8 + (lane & 3) * 2;
        float2 v0; v0.x = o_[nt][0]; v0.y = o_[nt][1];
        float2 v1; v1.x = o_[nt][2]; v1.y = o_[nt][3];
        *(float2*)&g_part[base0 + c] = v0;
        *(float2*)&g_part[base1 + c] = v1;
    }
    if ((lane & 3) == 0) {
        g_psum[((size_t)kvs * M_ + bb * S_ + r0) * HQ_ + h]       = rs0;
        g_psum[((size_t)kvs * M_ + bb * S_ + r0 + 8) * HQ_ + h]   = rs1;
    }
}

// ---------------- combine split-kv partials -> single fp16 y ----------------
__global__ void attn_combine_kernel() {
    int idx = blockIdx.x * blockDim.x + threadIdx.x;
    int r   = idx / (HQ_ * 24);
    int rem = idx - r * (HQ_ * 24);
    int h   = rem / 24;
    int c4  = (rem - h * 24) * 4;
    size_t o0 = ((size_t)r * HQ_ + h) * DV_ + c4;
    float4 p0 = *(float4*)&g_part[o0];
    float4 p1 = *(float4*)&g_part[(size_t)M_ * HQ_ * DV_ + o0];
    float s = g_psum[(size_t)r * HQ_ + h] + g_psum[(size_t)M_ * HQ_ + (size_t)r * HQ_ + h];
    float inv = 1.0f / s;
    *(unsigned*)&g_y[o0]     = pack2h((p0.x + p1.x) * inv, (p0.y + p1.y) * inv);
    *(unsigned*)&g_y[o0 + 2] = pack2h((p0.z + p1.z) * inv, (p0.w + p1.w) * inv);
}

// ---------------- launch ----------------
extern "C" void kernel_launch(void* const* d_in, const int* in_sizes, int n_in,
                              void* d_out, int out_size) {
    const float* x      = (const float*)d_in[0];
    const float* bn1_g  = (const float*)d_in[1];
    const float* bn1_ms = (const float*)d_in[2];
    const float* Wq     = (const float*)d_in[3];
    const float* Wk     = (const float*)d_in[4];
    const float* Wv     = (const float*)d_in[5];
    const float* qn_g   = (const float*)d_in[6];
    const float* qn_b   = (const float*)d_in[7];
    const float* kn_g   = (const float*)d_in[8];
    const float* kn_b   = (const float*)d_in[9];
    const float* vn_g   = (const float*)d_in[10];
    const float* vn_b   = (const float*)d_in[11];
    const float* Wo     = (const float*)d_in[12];
    const float* bo     = (const float*)d_in[13];
    const float* bn2_g  = (const float*)d_in[14];
    const float* bn2_ms = (const float*)d_in[15];
    float* out = (float*)d_out;

    __half *pqkvh, *phh, *pwt, *pwo, *py;
    cudaGetSymbolAddress((void**)&pqkvh, g_qkvh);
    cudaGetSymbolAddress((void**)&phh, g_hh);
    cudaGetSymbolAddress((void**)&pwt, g_wt);
    cudaGetSymbolAddress((void**)&pwo, g_wo);
    cudaGetSymbolAddress((void**)&py, g_y);

    cudaFuncSetAttribute((const void*)mma_gemm_kernel<128, true>,
                         cudaFuncAttributeMaxDynamicSharedMemorySize, 4 * 32768);
    cudaFuncSetAttribute((const void*)mma_gemm_kernel<64, false>,
                         cudaFuncAttributeMaxDynamicSharedMemorySize, 4 * 24576);
    cudaFuncSetAttribute(attn_mma_kernel, cudaFuncAttributeMaxDynamicSharedMemorySize, ATT_SMEM);

    // 1. rms_bn1 -> fp16
    bn1_kernel<<<(M_ * C_ / 4) / 256, 256>>>(x, bn1_g, bn1_ms, phh);
    // 2. Wo transpose
    transpose_h_kernel<<<dim3(C_/32, C_/32), dim3(32,8)>>>(Wo, pwo, C_, C_);
    // 3. packed QKV weight transpose
    transpose_qkv_kernel<<<dim3(NQKV/32, C_/32), dim3(32,8)>>>(Wq, Wk, Wv, pwt);
    // 4. merged QKV projection, 256 threads, fp16 out (profiled launch)
    mma_gemm_kernel<128, true><<<dim3(NQKV/128, M_/128), 256, 4 * 32768>>>(
        phh, pwt, pqkvh, M_, NQKV, C_, nullptr, nullptr, nullptr);
    // 5. merged LN (+RoPE), fp16 in
    ln_all_kernel<<<(M_ * 24) / 8, 256>>>(pqkvh, qn_g, qn_b, kn_g, kn_b, vn_g, vn_b);
    // 6. attention, split-kv x2
    attn_mma_kernel<<<dim3(S_ / 128, HQ_, B_ * 2), 256, ATT_SMEM>>>();
    // 7. combine partials -> y fp16
    attn_combine_kernel<<<(M_ * HQ_ * 24) / 256, 256>>>();
    // 8. out projection + bias + rms_bn2 -> d_out
    mma_gemm_kernel<64, false><<<dim3(C_/64, M_/128), 256, 4 * 24576>>>(
        py, pwo, out, M_, C_, HQ_*DV_, bo, bn2_g, bn2_ms);
}

// round 16
// speedup vs baseline: 1.5288x; 1.0096x over previous
#include <cuda_runtime.h>
#include <cuda_fp16.h>
#include <math.h>

// Problem constants
#define B_    2
#define S_    2048
#define C_    1536
#define HQ_   16
#define HKV_  4
#define DQK_  128
#define DV_   96
#define EPS_  1e-5f
#define CLIP_ 5.0f
#define M_    (B_*S_)          // 4096 rows
#define NQKV  2944             // 2048 q + 512 k + 384 v packed columns

// ---------------- scratch (device globals; no allocation) ----------------
__device__ __half g_qkvh[M_ * NQKV];          // packed fp16 QKV GEMM output
__device__ float g_part[2 * M_ * HQ_ * DV_];  // split-kv partial outputs
__device__ float g_psum[2 * M_ * HQ_];        // split-kv partial row sums

// fp16 operands
__device__ __half g_hh[M_ * C_];              // x converted to fp16 (bn1 folded into weights)
__device__ __half g_wt[NQKV * C_];            // packed Wq|Wk|Wv transposed, bn1-scaled
__device__ __half g_wo[C_ * C_];              // Wo transposed
__device__ __half g_y[M_ * HQ_ * DV_];        // attention output
__device__ __half g_qh[M_ * HQ_ * DQK_];      // q post-LN/RoPE
__device__ __half g_kh[M_ * HKV_ * DQK_];     // k post-LN/RoPE
__device__ __half g_vh[M_ * HKV_ * DV_];      // v post-LN

// ==================== helpers ====================
__device__ __forceinline__ unsigned smem_u32(const void* p) {
    unsigned a;
    asm("{ .reg .u64 t; cvta.to.shared.u64 t, %1; cvt.u32.u64 %0, t; }" : "=r"(a) : "l"(p));
    return a;
}

#define LDSM4(r0, r1, r2, r3, addr) \
    asm volatile("ldmatrix.sync.aligned.m8n8.x4.shared.b16 {%0,%1,%2,%3}, [%4];" \
        : "=r"(r0), "=r"(r1), "=r"(r2), "=r"(r3) : "r"(addr))

#define LDSM4T(r0, r1, r2, r3, addr) \
    asm volatile("ldmatrix.sync.aligned.m8n8.x4.trans.shared.b16 {%0,%1,%2,%3}, [%4];" \
        : "=r"(r0), "=r"(r1), "=r"(r2), "=r"(r3) : "r"(addr))

#define MMA16816(d, a0, a1, a2, a3, b0, b1) \
    asm volatile("mma.sync.aligned.m16n8k16.row.col.f32.f16.f16.f32 " \
        "{%0,%1,%2,%3}, {%4,%5,%6,%7}, {%8,%9}, {%0,%1,%2,%3};" \
        : "+f"((d)[0]), "+f"((d)[1]), "+f"((d)[2]), "+f"((d)[3]) \
        : "r"(a0), "r"(a1), "r"(a2), "r"(a3), "r"(b0), "r"(b1))

#define CPASYNC16(dst, src) \
    asm volatile("cp.async.cg.shared.global [%0], [%1], 16;" :: "r"(dst), "l"(src))
#define CPASYNC_COMMIT() asm volatile("cp.async.commit_group;" ::: "memory")
#define CPASYNC_WAIT2()  asm volatile("cp.async.wait_group 2;" ::: "memory")
#define CPASYNC_WAIT1()  asm volatile("cp.async.wait_group 1;" ::: "memory")
#define CPASYNC_WAIT0()  asm volatile("cp.async.wait_group 0;" ::: "memory")

__device__ __forceinline__ unsigned pack2h(float p0, float p1) {
    return (unsigned)__half_as_ushort(__float2half_rn(p0)) |
           ((unsigned)__half_as_ushort(__float2half_rn(p1)) << 16);
}
__device__ __forceinline__ float2 unpack2h(unsigned v) {
    float2 r;
    r.x = __half2float(__ushort_as_half((unsigned short)(v & 0xffff)));
    r.y = __half2float(__ushort_as_half((unsigned short)(v >> 16)));
    return r;
}

// ==================== stage 1: x -> fp16 (bn1 folded into weights) ====================
__global__ void cvt_kernel(const float* __restrict__ x, __half* __restrict__ hh) {
    int i = blockIdx.x * blockDim.x + threadIdx.x;        // float4 index
    float4 xv = ((const float4*)x)[i];
    *(unsigned*)&hh[i * 4]     = pack2h(xv.x, xv.y);
    *(unsigned*)&hh[i * 4 + 2] = pack2h(xv.z, xv.w);
}

// ---------------- weight transpose -> single fp16: W[K,N] -> Wt[N,K] ----------------
__global__ void transpose_h_kernel(const float* __restrict__ W,
                                   __half* __restrict__ Th,
                                   int K, int N) {
    __shared__ float t[32][33];
    int n0 = blockIdx.x * 32, k0 = blockIdx.y * 32;
    int tx = threadIdx.x, ty = threadIdx.y;   // 32 x 8
    #pragma unroll
    for (int i = 0; i < 32; i += 8)
        t[ty + i][tx] = W[(size_t)(k0 + ty + i) * N + n0 + tx];
    __syncthreads();
    #pragma unroll
    for (int i = 0; i < 32; i += 8)
        Th[(size_t)(n0 + ty + i) * K + k0 + tx] = __float2half_rn(t[tx][ty + i]);
}

// ---------------- packed QKV weight transpose, bn1 scale folded in ----------------
__global__ void transpose_qkv_kernel(const float* __restrict__ Wq,
                                     const float* __restrict__ Wk,
                                     const float* __restrict__ Wv,
                                     const float* __restrict__ bn1_g,
                                     const float* __restrict__ bn1_ms,
                                     __half* __restrict__ Th) {
    __shared__ float t[32][33];
    int n0 = blockIdx.x * 32, k0 = blockIdx.y * 32;
    int tx = threadIdx.x, ty = threadIdx.y;   // 32 x 8
    const float* W; int N; int nloc;
    if (n0 < HQ_ * DQK_)                  { W = Wq; N = HQ_ * DQK_;  nloc = n0; }
    else if (n0 < HQ_ * DQK_ + HKV_ * DQK_) { W = Wk; N = HKV_ * DQK_; nloc = n0 - HQ_ * DQK_; }
    else                                   { W = Wv; N = HKV_ * DV_;  nloc = n0 - HQ_ * DQK_ - HKV_ * DQK_; }
    #pragma unroll
    for (int i = 0; i < 32; i += 8)
        t[ty + i][tx] = W[(size_t)(k0 + ty + i) * N + nloc + tx];
    __syncthreads();
    float s = rsqrtf(bn1_ms[k0 + tx] + EPS_) * bn1_g[k0 + tx];   // per-k scale
    #pragma unroll
    for (int i = 0; i < 32; i += 8)
        Th[(size_t)(n0 + ty + i) * C_ + k0 + tx] = __float2half_rn(t[tx][ty + i] * s);
}

// ==================== mma.sync fp16 1-term GEMM, 256 threads, 4-stage ====================
template <int BN, bool HOUT>
__global__ __launch_bounds__(256, 1)
void mma_gemm_kernel(const __half* __restrict__ Ah, const __half* __restrict__ Bh,
                     void* __restrict__ Cm, int Mdim, int Ndim, int Kdim,
                     const float* __restrict__ bias,
                     const float* __restrict__ bn_g,
                     const float* __restrict__ bn_ms) {
    constexpr int WMC = (BN == 128) ? 2 : 4;
    constexpr int MSPAN = 128 / WMC;
    constexpr int A_T = MSPAN / 16;
    constexpr unsigned B_BYTES = (unsigned)BN * 128;
    constexpr unsigned SSZ = 16384 + B_BYTES;

    extern __shared__ __align__(1024) char sm[];
    const unsigned sb = smem_u32(sm);
    const int tid = threadIdx.x, wid = tid >> 5, lane = tid & 31;
    const int bm = blockIdx.y * 128, bn = blockIdx.x * BN;
    const int wm = wid % WMC, wn = wid / WMC;

    const __half* srcs[2] = {Ah, Bh};
    const int rowbase[2] = {bm, bn};
    const unsigned offs[2] = {0u, 16384u};
    const int KT = Kdim >> 6;

    auto load_tile_async = [&](int kt, int buf) {
        unsigned base = sb + (unsigned)buf * SSZ;
        #pragma unroll
        for (int p = 0; p < 2; p++) {
            int rows = (p == 0) ? 128 : BN;
            const __half* src = srcs[p] + (size_t)rowbase[p] * Kdim + kt * 64;
            for (int it = 0; it < rows / 32; it++) {
                int chunk = it * 256 + tid;
                int row = chunk >> 3, c = chunk & 7;
                unsigned off = row * 128 + c * 16;
                off ^= (off >> 3) & 0x70;
                CPASYNC16(base + offs[p] + off, (const void*)(src + (size_t)row * Kdim + c * 8));
            }
        }
        CPASYNC_COMMIT();
    };

    float acc[A_T][4][4];
    #pragma unroll
    for (int a = 0; a < A_T; a++)
        #pragma unroll
        for (int n = 0; n < 4; n++)
            #pragma unroll
            for (int q = 0; q < 4; q++) acc[a][n][q] = 0.f;

    const int a_row  = wm * MSPAN + (lane & 15);
    const unsigned a_byte = (lane >> 4) << 4;
    const int b_row  = wn * 32 + (lane & 7) + ((lane >> 4) << 3);
    const unsigned b_byte = ((lane >> 3) & 1) << 4;

    load_tile_async(0, 0);
    load_tile_async(1, 1);
    load_tile_async(2, 2);

    for (int kt = 0; kt < KT; kt++) {
        int b = kt & 3;
        if (kt + 2 < KT)      CPASYNC_WAIT2();
        else if (kt + 1 < KT) CPASYNC_WAIT1();
        else                  CPASYNC_WAIT0();
        __syncthreads();
        if (kt + 3 < KT) load_tile_async(kt + 3, (kt + 3) & 3);

        unsigned baseA = sb + (unsigned)b * SSZ;
        unsigned baseB = baseA + 16384;

        #pragma unroll
        for (int ks = 0; ks < 4; ks++) {
            unsigned bh[8];
            #pragma unroll
            for (int p = 0; p < 2; p++) {
                unsigned off = (unsigned)(b_row + p * 16) * 128 + b_byte + ks * 32;
                off ^= (off >> 3) & 0x70;
                LDSM4(bh[p*4+0], bh[p*4+1], bh[p*4+2], bh[p*4+3], baseB + off);
            }
            #pragma unroll
            for (int a = 0; a < A_T; a++) {
                unsigned offA = (unsigned)(a_row + a * 16) * 128 + a_byte + ks * 32;
                offA ^= (offA >> 3) & 0x70;
                unsigned ah0, ah1, ah2, ah3;
                LDSM4(ah0, ah1, ah2, ah3, baseA + offA);
                #pragma unroll
                for (int nat = 0; nat < 4; nat++) {
                    int p = nat >> 1, q = nat & 1;
                    MMA16816(acc[a][nat], ah0, ah1, ah2, ah3,
                             bh[p*4 + q*2], bh[p*4 + q*2 + 1]);
                }
            }
        }
    }

    #pragma unroll
    for (int a = 0; a < A_T; a++) {
        int r0 = bm + wm * MSPAN + a * 16 + (lane >> 2);
        #pragma unroll
        for (int nat = 0; nat < 4; nat++) {
            int c = bn + wn * 32 + nat * 8 + (lane & 3) * 2;
            float f0 = 1.f, f1 = 1.f, b0 = 0.f, b1 = 0.f;
            if (bias) { b0 = bias[c]; b1 = bias[c + 1]; }
            if (bn_g) {
                f0 = rsqrtf(bn_ms[c] + EPS_) * bn_g[c];
                f1 = rsqrtf(bn_ms[c + 1] + EPS_) * bn_g[c + 1];
            }
            float u0 = (acc[a][nat][0] + b0) * f0;
            float u1 = (acc[a][nat][1] + b1) * f1;
            float u2 = (acc[a][nat][2] + b0) * f0;
            float u3 = (acc[a][nat][3] + b1) * f1;
            if (HOUT) {
                __half* Ch = (__half*)Cm;
                *(unsigned*)&Ch[(size_t)r0 * Ndim + c]       = pack2h(u0, u1);
                *(unsigned*)&Ch[(size_t)(r0 + 8) * Ndim + c] = pack2h(u2, u3);
            } else {
                float* Cf = (float*)Cm;
                float2 v0; v0.x = u0; v0.y = u1;
                float2 v1; v1.x = u2; v1.y = u3;
                *(float2*)&Cf[(size_t)r0 * Ndim + c]       = v0;
                *(float2*)&Cf[(size_t)(r0 + 8) * Ndim + c] = v1;
            }
        }
    }
}

// ---------------- merged LN (+RoPE), fp16 in -> fp16 out ----------------
__global__ void ln_all_kernel(const __half* __restrict__ qkv,
                              const float* __restrict__ qn_g, const float* __restrict__ qn_b,
                              const float* __restrict__ kn_g, const float* __restrict__ kn_b,
                              const float* __restrict__ vn_g, const float* __restrict__ vn_b) {
    int w    = (blockIdx.x * blockDim.x + threadIdx.x) >> 5;
    int lane = threadIdx.x & 31;
    int row  = w / 24, slot = w - row * 24;
    if (row >= M_) return;
    int s = row & (S_ - 1);

    if (slot < 20) {
        bool isq = (slot < 16);
        const __half* p; const float *g, *b; __half* dsth; size_t dst;
        if (isq) {
            p = qkv + (size_t)row * NQKV + slot * 128;
            g = qn_g; b = qn_b; dsth = g_qh;
            dst = ((size_t)row * HQ_ + slot) * 128;
        } else {
            p = qkv + (size_t)row * NQKV + 2048 + (slot - 16) * 128;
            g = kn_g; b = kn_b; dsth = g_kh;
            dst = ((size_t)row * HKV_ + (slot - 16)) * 128;
        }
        float2 v0 = unpack2h(*(const unsigned*)&p[2 * lane]);
        float2 v1 = unpack2h(*(const unsigned*)&p[2 * lane + 64]);

        float sum = v0.x + v0.y + v1.x + v1.y;
        #pragma unroll
        for (int o = 16; o > 0; o >>= 1) sum += __shfl_xor_sync(0xffffffffu, sum, o);
        float mu = sum * (1.f / 128.f);

        float d0 = v0.x - mu, d1 = v0.y - mu, d2 = v1.x - mu, d3 = v1.y - mu;
        float sq = d0 * d0 + d1 * d1 + d2 * d2 + d3 * d3;
        #pragma unroll
        for (int o = 16; o > 0; o >>= 1) sq += __shfl_xor_sync(0xffffffffu, sq, o);
        float inv = rsqrtf(sq * (1.f / 128.f) + EPS_);

        int i0 = 2 * lane, i1 = 2 * lane + 64;
        float a0 = d0 * inv * g[i0]     + b[i0];
        float a1 = d1 * inv * g[i0 + 1] + b[i0 + 1];
        float a2 = d2 * inv * g[i1]     + b[i1];
        float a3 = d3 * inv * g[i1 + 1] + b[i1 + 1];

        const float kl = logf(1985.0f) / 63.0f;
        float f0 = 1.0f / ((float)lane        + expf((float)lane        * kl));
        float f1 = 1.0f / ((float)(lane + 32) + expf((float)(lane + 32) * kl));
        float c0, s0, c1, s1;
        sincosf((float)s * f0, &s0, &c0);
        sincosf((float)s * f1, &s1, &c1);

        float o0 = a0 * c0 - a1 * s0, o1 = a1 * c0 + a0 * s0;
        float o2 = a2 * c1 - a3 * s1, o3 = a3 * c1 + a2 * s1;

        *(unsigned*)&dsth[dst + i0] = pack2h(o0, o1);
        *(unsigned*)&dsth[dst + i1] = pack2h(o2, o3);
    } else {
        const __half* p = qkv + (size_t)row * NQKV + 2560 + (slot - 20) * 96;
        size_t dst = ((size_t)row * HKV_ + (slot - 20)) * 96;
        float x0 = __half2float(p[lane]);
        float x1 = __half2float(p[lane + 32]);
        float x2 = __half2float(p[lane + 64]);
        float sum = x0 + x1 + x2;
        #pragma unroll
        for (int o = 16; o > 0; o >>= 1) sum += __shfl_xor_sync(0xffffffffu, sum, o);
        float mu = sum * (1.f / 96.f);
        float d0 = x0 - mu, d1 = x1 - mu, d2 = x2 - mu;
        float sq = d0 * d0 + d1 * d1 + d2 * d2;
        #pragma unroll
        for (int o = 16; o > 0; o >>= 1) sq += __shfl_xor_sync(0xffffffffu, sq, o);
        float inv = rsqrtf(sq * (1.f / 96.f) + EPS_);
        g_vh[dst + lane]      = __float2half_rn(d0 * inv * vn_g[lane]      + vn_b[lane]);
        g_vh[dst + lane + 32] = __float2half_rn(d1 * inv * vn_g[lane + 32] + vn_b[lane + 32]);
        g_vh[dst + lane + 64] = __float2half_rn(d2 * inv * vn_g[lane + 64] + vn_b[lane + 64]);
    }
}

// ==================== mma.sync fp16 attention, split-kv x2, MUFU/HMMA interleave ====================
#define Q_BYTES    32768
#define K_BYTES    16384
#define V_STRIDE   208
#define V_BYTES    (64 * V_STRIDE)
#define KV_BUF     (K_BYTES + V_BYTES)          // 29696
#define ATT_SMEM   (Q_BYTES + 2 * KV_BUF)       // 92160

__global__ __launch_bounds__(256, 1)
void attn_mma_kernel() {
    extern __shared__ __align__(1024) char sm[];
    const unsigned sb = smem_u32(sm);
    const int qb  = blockIdx.x;
    const int h   = blockIdx.y;
    const int bb  = blockIdx.z >> 1;
    const int kvs = blockIdx.z & 1;
    const int hk = h & (HKV_ - 1);
    const int tid = threadIdx.x, wid = tid >> 5, lane = tid & 31;

    {   // Q loads (grouped with kv tile 0)
        #pragma unroll
        for (int it = 0; it < 8; it++) {
            int chunk = it * 256 + tid;
            int row = chunk >> 4, c = chunk & 15;
            unsigned off = row * 256 + c * 16;
            off ^= (off >> 4) & 0x70;
            const __half* src = g_qh +
                ((size_t)(bb * S_ + qb * 128 + row) * HQ_ + h) * DQK_ + c * 8;
            CPASYNC16(sb + off, (const void*)src);
        }
    }

    auto load_kv = [&](int kt, int buf) {
        unsigned base = sb + Q_BYTES + buf * KV_BUF;
        int s0 = (kvs * 16 + kt) * 64;
        #pragma unroll
        for (int it = 0; it < 4; it++) {
            int chunk = it * 256 + tid;
            int row = chunk >> 4, c = chunk & 15;
            unsigned off = row * 256 + c * 16;
            off ^= (off >> 4) & 0x70;
            const __half* src = g_kh +
                ((size_t)(bb * S_ + s0 + row) * HKV_ + hk) * DQK_ + c * 8;
            CPASYNC16(base + off, (const void*)src);
        }
        #pragma unroll
        for (int it = 0; it < 3; it++) {
            int chunk = it * 256 + tid;
            int row = chunk / 12, c = chunk % 12;
            unsigned off = row * V_STRIDE + c * 16;
            const __half* src = g_vh +
                ((size_t)(bb * S_ + s0 + row) * HKV_ + hk) * DV_ + c * 8;
            CPASYNC16(base + K_BYTES + off, (const void*)src);
        }
        CPASYNC_COMMIT();
    };

    load_kv(0, 0);

    float o_[12][4];
    #pragma unroll
    for (int t = 0; t < 12; t++)
        #pragma unroll
        for (int q = 0; q < 4; q++) o_[t][q] = 0.f;
    float rs0 = 0.f, rs1 = 0.f;

    const float scale = 0.08838834764831845f;
    const int a_row  = wid * 16 + (lane & 15);
    const unsigned a_byte = (lane >> 4) << 4;
    const int b_rowc = (lane & 7) + ((lane >> 4) << 3);
    const unsigned b_byte = ((lane >> 3) & 1) << 4;
    const unsigned voff = (unsigned)(lane & 15) * V_STRIDE + ((lane >> 4) << 4);

    const int NT = 16;
    for (int kb = 0; kb < NT; kb++) {
        int b = kb & 1;
        CPASYNC_WAIT0();
        __syncthreads();
        if (kb + 1 < NT) load_kv(kb + 1, b ^ 1);

        unsigned baseK = sb + Q_BYTES + b * KV_BUF;
        unsigned baseV = baseK + K_BYTES;

        float sc[8][4];
        #pragma unroll
        for (int t = 0; t < 8; t++)
            #pragma unroll
            for (int q = 0; q < 4; q++) sc[t][q] = 0.f;

        #pragma unroll
        for (int ks = 0; ks < 8; ks++) {
            unsigned offA = (unsigned)a_row * 256 + a_byte + ks * 32;
            offA ^= (offA >> 4) & 0x70;
            unsigned qh0, qh1, qh2, qh3;
            LDSM4(qh0, qh1, qh2, qh3, sb + offA);
            #pragma unroll
            for (int p = 0; p < 4; p++) {
                unsigned offB = (unsigned)(p * 16 + b_rowc) * 256 + b_byte + ks * 32;
                offB ^= (offB >> 4) & 0x70;
                unsigned kh0, kh1, kh2, kh3;
                LDSM4(kh0, kh1, kh2, kh3, baseK + offB);
                MMA16816(sc[2*p],   qh0, qh1, qh2, qh3, kh0, kh1);
                MMA16816(sc[2*p+1], qh0, qh1, qh2, qh3, kh2, kh3);
            }
        }

        // softcap one j-group; interleave MUFU with PV tensor work
        unsigned ah[4][4];
        auto docap = [&](int j) {
            #pragma unroll
            for (int tt = 0; tt < 2; tt++) {
                int t = 2 * j + tt;
                #pragma unroll
                for (int q = 0; q < 4; q++) {
                    float l = sc[t][q] * scale;
                    float e = __expf(0.4f * l);
                    float th = 1.f - __fdividef(2.f, e + 1.f);
                    float pp = __expf(CLIP_ * th);
                    sc[t][q] = pp;
                    if (q < 2) rs0 += pp; else rs1 += pp;
                }
            }
            ah[j][0] = pack2h(sc[2*j][0],   sc[2*j][1]);
            ah[j][1] = pack2h(sc[2*j][2],   sc[2*j][3]);
            ah[j][2] = pack2h(sc[2*j+1][0], sc[2*j+1][1]);
            ah[j][3] = pack2h(sc[2*j+1][2], sc[2*j+1][3]);
        };

        docap(0);
        #pragma unroll
        for (int j = 0; j < 4; j++) {
            #pragma unroll
            for (int ct = 0; ct < 3; ct++) {
                #pragma unroll
                for (int half = 0; half < 2; half++) {
                    unsigned a0 = voff + j * (16 * V_STRIDE) + ct * 64 + half * 32;
                    unsigned vh0, vh1, vh2, vh3;
                    LDSM4T(vh0, vh1, vh2, vh3, baseV + a0);
                    int nt = ct * 4 + half * 2;
                    MMA16816(o_[nt],   ah[j][0], ah[j][1], ah[j][2], ah[j][3], vh0, vh1);
                    MMA16816(o_[nt+1], ah[j][0], ah[j][1], ah[j][2], ah[j][3], vh2, vh3);
                }
            }
            if (j < 3) docap(j + 1);
        }
    }

    rs0 += __shfl_xor_sync(0xffffffffu, rs0, 1);
    rs0 += __shfl_xor_sync(0xffffffffu, rs0, 2);
    rs1 += __shfl_xor_sync(0xffffffffu, rs1, 1);
    rs1 += __shfl_xor_sync(0xffffffffu, rs1, 2);

    int r0 = qb * 128 + wid * 16 + (lane >> 2);
    size_t base0 = (((size_t)kvs * M_ + bb * S_ + r0) * HQ_ + h) * DV_;
    size_t base1 = base0 + 8 * (size_t)(HQ_ * DV_);
    #pragma unroll
    for (int nt = 0; nt < 12; nt++) {
        int c = nt * 8 + (lane & 3) * 2;
        float2 v0; v0.x = o_[nt][0]; v0.y = o_[nt][1];
        float2 v1; v1.x = o_[nt][2]; v1.y = o_[nt][3];
        *(float2*)&g_part[base0 + c] = v0;
        *(float2*)&g_part[base1 + c] = v1;
    }
    if ((lane & 3) == 0) {
        g_psum[((size_t)kvs * M_ + bb * S_ + r0) * HQ_ + h]       = rs0;
        g_psum[((size_t)kvs * M_ + bb * S_ + r0 + 8) * HQ_ + h]   = rs1;
    }
}

// ---------------- combine split-kv partials -> single fp16 y ----------------
__global__ void attn_combine_kernel() {
    int idx = blockIdx.x * blockDim.x + threadIdx.x;
    int r   = idx / (HQ_ * 24);
    int rem = idx - r * (HQ_ * 24);
    int h   = rem / 24;
    int c4  = (rem - h * 24) * 4;
    size_t o0 = ((size_t)r * HQ_ + h) * DV_ + c4;
    float4 p0 = *(float4*)&g_part[o0];
    float4 p1 = *(float4*)&g_part[(size_t)M_ * HQ_ * DV_ + o0];
    float s = g_psum[(size_t)r * HQ_ + h] + g_psum[(size_t)M_ * HQ_ + (size_t)r * HQ_ + h];
    float inv = 1.0f / s;
    *(unsigned*)&g_y[o0]     = pack2h((p0.x + p1.x) * inv, (p0.y + p1.y) * inv);
    *(unsigned*)&g_y[o0 + 2] = pack2h((p0.z + p1.z) * inv, (p0.w + p1.w) * inv);
}

// ---------------- launch ----------------
extern "C" void kernel_launch(void* const* d_in, const int* in_sizes, int n_in,
                              void* d_out, int out_size) {
    const float* x      = (const float*)d_in[0];
    const float* bn1_g  = (const float*)d_in[1];
    const float* bn1_ms = (const float*)d_in[2];
    const float* Wq     = (const float*)d_in[3];
    const float* Wk     = (const float*)d_in[4];
    const float* Wv     = (const float*)d_in[5];
    const float* qn_g   = (const float*)d_in[6];
    const float* qn_b   = (const float*)d_in[7];
    const float* kn_g   = (const float*)d_in[8];
    const float* kn_b   = (const float*)d_in[9];
    const float* vn_g   = (const float*)d_in[10];
    const float* vn_b   = (const float*)d_in[11];
    const float* Wo     = (const float*)d_in[12];
    const float* bo     = (const float*)d_in[13];
    const float* bn2_g  = (const float*)d_in[14];
    const float* bn2_ms = (const float*)d_in[15];
    float* out = (float*)d_out;

    __half *pqkvh, *phh, *pwt, *pwo, *py;
    cudaGetSymbolAddress((void**)&pqkvh, g_qkvh);
    cudaGetSymbolAddress((void**)&phh, g_hh);
    cudaGetSymbolAddress((void**)&pwt, g_wt);
    cudaGetSymbolAddress((void**)&pwo, g_wo);
    cudaGetSymbolAddress((void**)&py, g_y);

    cudaFuncSetAttribute((const void*)mma_gemm_kernel<128, true>,
                         cudaFuncAttributeMaxDynamicSharedMemorySize, 4 * 32768);
    cudaFuncSetAttribute((const void*)mma_gemm_kernel<64, false>,
                         cudaFuncAttributeMaxDynamicSharedMemorySize, 4 * 24576);
    cudaFuncSetAttribute(attn_mma_kernel, cudaFuncAttributeMaxDynamicSharedMemorySize, ATT_SMEM);

    // 1. x -> fp16 (bn1 folded into weights)
    cvt_kernel<<<(M_ * C_ / 4) / 256, 256>>>(x, phh);
    // 2. Wo transpose
    transpose_h_kernel<<<dim3(C_/32, C_/32), dim3(32,8)>>>(Wo, pwo, C_, C_);
    // 3. packed QKV weight transpose with bn1 scale
    transpose_qkv_kernel<<<dim3(NQKV/32, C_/32), dim3(32,8)>>>(Wq, Wk, Wv, bn1_g, bn1_ms, pwt);
    // 4. merged QKV projection, 256 threads, fp16 out (profiled launch)
    mma_gemm_kernel<128, true><<<dim3(NQKV/128, M_/128), 256, 4 * 32768>>>(
        phh, pwt, pqkvh, M_, NQKV, C_, nullptr, nullptr, nullptr);
    // 5. merged LN (+RoPE), fp16 in
    ln_all_kernel<<<(M_ * 24) / 8, 256>>>(pqkvh, qn_g, qn_b, kn_g, kn_b, vn_g, vn_b);
    // 6. attention, split-kv x2, MUFU/HMMA interleaved softcap
    attn_mma_kernel<<<dim3(S_ / 128, HQ_, B_ * 2), 256, ATT_SMEM>>>();
    // 7. combine partials -> y fp16
    attn_combine_kernel<<<(M_ * HQ_ * 24) / 256, 256>>>();
    // 8. out projection + bias + rms_bn2 -> d_out
    mma_gemm_kernel<64, false><<<dim3(C_/64, M_/128), 256, 4 * 24576>>>(
        py, pwo, out, M_, C_, HQ_*DV_, bo, bn2_g, bn2_ms);
}

// round 17
// speedup vs baseline: 1.5489x; 1.0132x over previous
#include <cuda_runtime.h>
#include <cuda_fp16.h>
#include <math.h>

// Problem constants
#define B_    2
#define S_    2048
#define C_    1536
#define HQ_   16
#define HKV_  4
#define DQK_  128
#define DV_   96
#define EPS_  1e-5f
#define CLIP_ 5.0f
#define M_    (B_*S_)          // 4096 rows
#define NQKV  2944             // 2048 q + 512 k + 384 v packed columns

// ---------------- scratch (device globals; no allocation) ----------------
__device__ __half g_qkvh[M_ * NQKV];          // packed fp16 QKV GEMM output
__device__ float g_part[2 * M_ * HQ_ * DV_];  // split-kv partial outputs
__device__ float g_psum[2 * M_ * HQ_];        // split-kv partial row sums

// fp16 operands
__device__ __half g_hh[M_ * C_];              // x converted to fp16 (bn1 folded into weights)
__device__ __half g_wt[NQKV * C_];            // packed Wq|Wk|Wv transposed, bn1-scaled
__device__ __half g_wo[C_ * C_];              // Wo transposed
__device__ __half g_y[M_ * HQ_ * DV_];        // attention output
__device__ __half g_qh[M_ * HQ_ * DQK_];      // q post-LN/RoPE
__device__ __half g_kh[M_ * HKV_ * DQK_];     // k post-LN/RoPE
__device__ __half g_vh[M_ * HKV_ * DV_];      // v post-LN

// ==================== helpers ====================
__device__ __forceinline__ unsigned smem_u32(const void* p) {
    unsigned a;
    asm("{ .reg .u64 t; cvta.to.shared.u64 t, %1; cvt.u32.u64 %0, t; }" : "=r"(a) : "l"(p));
    return a;
}

#define LDSM4(r0, r1, r2, r3, addr) \
    asm volatile("ldmatrix.sync.aligned.m8n8.x4.shared.b16 {%0,%1,%2,%3}, [%4];" \
        : "=r"(r0), "=r"(r1), "=r"(r2), "=r"(r3) : "r"(addr))

#define LDSM4T(r0, r1, r2, r3, addr) \
    asm volatile("ldmatrix.sync.aligned.m8n8.x4.trans.shared.b16 {%0,%1,%2,%3}, [%4];" \
        : "=r"(r0), "=r"(r1), "=r"(r2), "=r"(r3) : "r"(addr))

#define MMA16816(d, a0, a1, a2, a3, b0, b1) \
    asm volatile("mma.sync.aligned.m16n8k16.row.col.f32.f16.f16.f32 " \
        "{%0,%1,%2,%3}, {%4,%5,%6,%7}, {%8,%9}, {%0,%1,%2,%3};" \
        : "+f"((d)[0]), "+f"((d)[1]), "+f"((d)[2]), "+f"((d)[3]) \
        : "r"(a0), "r"(a1), "r"(a2), "r"(a3), "r"(b0), "r"(b1))

#define CPASYNC16(dst, src) \
    asm volatile("cp.async.cg.shared.global [%0], [%1], 16;" :: "r"(dst), "l"(src))
#define CPASYNC_COMMIT() asm volatile("cp.async.commit_group;" ::: "memory")
#define CPASYNC_WAIT2()  asm volatile("cp.async.wait_group 2;" ::: "memory")
#define CPASYNC_WAIT1()  asm volatile("cp.async.wait_group 1;" ::: "memory")
#define CPASYNC_WAIT0()  asm volatile("cp.async.wait_group 0;" ::: "memory")

__device__ __forceinline__ unsigned pack2h(float p0, float p1) {
    return (unsigned)__half_as_ushort(__float2half_rn(p0)) |
           ((unsigned)__half_as_ushort(__float2half_rn(p1)) << 16);
}
__device__ __forceinline__ float2 unpack2h(unsigned v) {
    float2 r;
    r.x = __half2float(__ushort_as_half((unsigned short)(v & 0xffff)));
    r.y = __half2float(__ushort_as_half((unsigned short)(v >> 16)));
    return r;
}

// ==================== stage 1: x -> fp16 (bn1 folded into weights) ====================
__global__ void cvt_kernel(const float* __restrict__ x, __half* __restrict__ hh) {
    int i = blockIdx.x * blockDim.x + threadIdx.x;        // float4 index
    float4 xv = ((const float4*)x)[i];
    *(unsigned*)&hh[i * 4]     = pack2h(xv.x, xv.y);
    *(unsigned*)&hh[i * 4 + 2] = pack2h(xv.z, xv.w);
}

// ---------------- weight transpose -> single fp16: W[K,N] -> Wt[N,K] ----------------
__global__ void transpose_h_kernel(const float* __restrict__ W,
                                   __half* __restrict__ Th,
                                   int K, int N) {
    __shared__ float t[32][33];
    int n0 = blockIdx.x * 32, k0 = blockIdx.y * 32;
    int tx = threadIdx.x, ty = threadIdx.y;   // 32 x 8
    #pragma unroll
    for (int i = 0; i < 32; i += 8)
        t[ty + i][tx] = W[(size_t)(k0 + ty + i) * N + n0 + tx];
    __syncthreads();
    #pragma unroll
    for (int i = 0; i < 32; i += 8)
        Th[(size_t)(n0 + ty + i) * K + k0 + tx] = __float2half_rn(t[tx][ty + i]);
}

// ---------------- packed QKV weight transpose, bn1 scale folded in ----------------
__global__ void transpose_qkv_kernel(const float* __restrict__ Wq,
                                     const float* __restrict__ Wk,
                                     const float* __restrict__ Wv,
                                     const float* __restrict__ bn1_g,
                                     const float* __restrict__ bn1_ms,
                                     __half* __restrict__ Th) {
    __shared__ float t[32][33];
    int n0 = blockIdx.x * 32, k0 = blockIdx.y * 32;
    int tx = threadIdx.x, ty = threadIdx.y;   // 32 x 8
    const float* W; int N; int nloc;
    if (n0 < HQ_ * DQK_)                  { W = Wq; N = HQ_ * DQK_;  nloc = n0; }
    else if (n0 < HQ_ * DQK_ + HKV_ * DQK_) { W = Wk; N = HKV_ * DQK_; nloc = n0 - HQ_ * DQK_; }
    else                                   { W = Wv; N = HKV_ * DV_;  nloc = n0 - HQ_ * DQK_ - HKV_ * DQK_; }
    #pragma unroll
    for (int i = 0; i < 32; i += 8)
        t[ty + i][tx] = W[(size_t)(k0 + ty + i) * N + nloc + tx];
    __syncthreads();
    float s = rsqrtf(bn1_ms[k0 + tx] + EPS_) * bn1_g[k0 + tx];   // per-k scale
    #pragma unroll
    for (int i = 0; i < 32; i += 8)
        Th[(size_t)(n0 + ty + i) * C_ + k0 + tx] = __float2half_rn(t[tx][ty + i] * s);
}

// ==================== mma.sync fp16 1-term GEMM, 256 threads, 4-stage ====================
template <int BN, bool HOUT>
__global__ __launch_bounds__(256, 1)
void mma_gemm_kernel(const __half* __restrict__ Ah, const __half* __restrict__ Bh,
                     void* __restrict__ Cm, int Mdim, int Ndim, int Kdim,
                     const float* __restrict__ bias,
                     const float* __restrict__ bn_g,
                     const float* __restrict__ bn_ms) {
    constexpr int WMC = (BN == 128) ? 2 : 4;
    constexpr int MSPAN = 128 / WMC;
    constexpr int A_T = MSPAN / 16;
    constexpr unsigned B_BYTES = (unsigned)BN * 128;
    constexpr unsigned SSZ = 16384 + B_BYTES;

    extern __shared__ __align__(1024) char sm[];
    const unsigned sb = smem_u32(sm);
    const int tid = threadIdx.x, wid = tid >> 5, lane = tid & 31;
    const int bm = blockIdx.y * 128, bn = blockIdx.x * BN;
    const int wm = wid % WMC, wn = wid / WMC;

    const __half* srcs[2] = {Ah, Bh};
    const int rowbase[2] = {bm, bn};
    const unsigned offs[2] = {0u, 16384u};
    const int KT = Kdim >> 6;

    auto load_tile_async = [&](int kt, int buf) {
        unsigned base = sb + (unsigned)buf * SSZ;
        #pragma unroll
        for (int p = 0; p < 2; p++) {
            int rows = (p == 0) ? 128 : BN;
            const __half* src = srcs[p] + (size_t)rowbase[p] * Kdim + kt * 64;
            for (int it = 0; it < rows / 32; it++) {
                int chunk = it * 256 + tid;
                int row = chunk >> 3, c = chunk & 7;
                unsigned off = row * 128 + c * 16;
                off ^= (off >> 3) & 0x70;
                CPASYNC16(base + offs[p] + off, (const void*)(src + (size_t)row * Kdim + c * 8));
            }
        }
        CPASYNC_COMMIT();
    };

    float acc[A_T][4][4];
    #pragma unroll
    for (int a = 0; a < A_T; a++)
        #pragma unroll
        for (int n = 0; n < 4; n++)
            #pragma unroll
            for (int q = 0; q < 4; q++) acc[a][n][q] = 0.f;

    const int a_row  = wm * MSPAN + (lane & 15);
    const unsigned a_byte = (lane >> 4) << 4;
    const int b_row  = wn * 32 + (lane & 7) + ((lane >> 4) << 3);
    const unsigned b_byte = ((lane >> 3) & 1) << 4;

    load_tile_async(0, 0);
    load_tile_async(1, 1);
    load_tile_async(2, 2);

    for (int kt = 0; kt < KT; kt++) {
        int b = kt & 3;
        if (kt + 2 < KT)      CPASYNC_WAIT2();
        else if (kt + 1 < KT) CPASYNC_WAIT1();
        else                  CPASYNC_WAIT0();
        __syncthreads();
        if (kt + 3 < KT) load_tile_async(kt + 3, (kt + 3) & 3);

        unsigned baseA = sb + (unsigned)b * SSZ;
        unsigned baseB = baseA + 16384;

        #pragma unroll
        for (int ks = 0; ks < 4; ks++) {
            unsigned bh[8];
            #pragma unroll
            for (int p = 0; p < 2; p++) {
                unsigned off = (unsigned)(b_row + p * 16) * 128 + b_byte + ks * 32;
                off ^= (off >> 3) & 0x70;
                LDSM4(bh[p*4+0], bh[p*4+1], bh[p*4+2], bh[p*4+3], baseB + off);
            }
            #pragma unroll
            for (int a = 0; a < A_T; a++) {
                unsigned offA = (unsigned)(a_row + a * 16) * 128 + a_byte + ks * 32;
                offA ^= (offA >> 3) & 0x70;
                unsigned ah0, ah1, ah2, ah3;
                LDSM4(ah0, ah1, ah2, ah3, baseA + offA);
                #pragma unroll
                for (int nat = 0; nat < 4; nat++) {
                    int p = nat >> 1, q = nat & 1;
                    MMA16816(acc[a][nat], ah0, ah1, ah2, ah3,
                             bh[p*4 + q*2], bh[p*4 + q*2 + 1]);
                }
            }
        }
    }

    #pragma unroll
    for (int a = 0; a < A_T; a++) {
        int r0 = bm + wm * MSPAN + a * 16 + (lane >> 2);
        #pragma unroll
        for (int nat = 0; nat < 4; nat++) {
            int c = bn + wn * 32 + nat * 8 + (lane & 3) * 2;
            float f0 = 1.f, f1 = 1.f, b0 = 0.f, b1 = 0.f;
            if (bias) { b0 = bias[c]; b1 = bias[c + 1]; }
            if (bn_g) {
                f0 = rsqrtf(bn_ms[c] + EPS_) * bn_g[c];
                f1 = rsqrtf(bn_ms[c + 1] + EPS_) * bn_g[c + 1];
            }
            float u0 = (acc[a][nat][0] + b0) * f0;
            float u1 = (acc[a][nat][1] + b1) * f1;
            float u2 = (acc[a][nat][2] + b0) * f0;
            float u3 = (acc[a][nat][3] + b1) * f1;
            if (HOUT) {
                __half* Ch = (__half*)Cm;
                *(unsigned*)&Ch[(size_t)r0 * Ndim + c]       = pack2h(u0, u1);
                *(unsigned*)&Ch[(size_t)(r0 + 8) * Ndim + c] = pack2h(u2, u3);
            } else {
                float* Cf = (float*)Cm;
                float2 v0; v0.x = u0; v0.y = u1;
                float2 v1; v1.x = u2; v1.y = u3;
                *(float2*)&Cf[(size_t)r0 * Ndim + c]       = v0;
                *(float2*)&Cf[(size_t)(r0 + 8) * Ndim + c] = v1;
            }
        }
    }
}

// ---------------- merged LN (+RoPE), fp16 in -> fp16 out ----------------
__global__ void ln_all_kernel(const __half* __restrict__ qkv,
                              const float* __restrict__ qn_g, const float* __restrict__ qn_b,
                              const float* __restrict__ kn_g, const float* __restrict__ kn_b,
                              const float* __restrict__ vn_g, const float* __restrict__ vn_b) {
    int w    = (blockIdx.x * blockDim.x + threadIdx.x) >> 5;
    int lane = threadIdx.x & 31;
    int row  = w / 24, slot = w - row * 24;
    if (row >= M_) return;
    int s = row & (S_ - 1);

    if (slot < 20) {
        bool isq = (slot < 16);
        const __half* p; const float *g, *b; __half* dsth; size_t dst;
        if (isq) {
            p = qkv + (size_t)row * NQKV + slot * 128;
            g = qn_g; b = qn_b; dsth = g_qh;
            dst = ((size_t)row * HQ_ + slot) * 128;
        } else {
            p = qkv + (size_t)row * NQKV + 2048 + (slot - 16) * 128;
            g = kn_g; b = kn_b; dsth = g_kh;
            dst = ((size_t)row * HKV_ + (slot - 16)) * 128;
        }
        float2 v0 = unpack2h(*(const unsigned*)&p[2 * lane]);
        float2 v1 = unpack2h(*(const unsigned*)&p[2 * lane + 64]);

        float sum = v0.x + v0.y + v1.x + v1.y;
        #pragma unroll
        for (int o = 16; o > 0; o >>= 1) sum += __shfl_xor_sync(0xffffffffu, sum, o);
        float mu = sum * (1.f / 128.f);

        float d0 = v0.x - mu, d1 = v0.y - mu, d2 = v1.x - mu, d3 = v1.y - mu;
        float sq = d0 * d0 + d1 * d1 + d2 * d2 + d3 * d3;
        #pragma unroll
        for (int o = 16; o > 0; o >>= 1) sq += __shfl_xor_sync(0xffffffffu, sq, o);
        float inv = rsqrtf(sq * (1.f / 128.f) + EPS_);

        int i0 = 2 * lane, i1 = 2 * lane + 64;
        float a0 = d0 * inv * g[i0]     + b[i0];
        float a1 = d1 * inv * g[i0 + 1] + b[i0 + 1];
        float a2 = d2 * inv * g[i1]     + b[i1];
        float a3 = d3 * inv * g[i1 + 1] + b[i1 + 1];

        const float kl = logf(1985.0f) / 63.0f;
        float f0 = 1.0f / ((float)lane        + expf((float)lane        * kl));
        float f1 = 1.0f / ((float)(lane + 32) + expf((float)(lane + 32) * kl));
        float c0, s0, c1, s1;
        sincosf((float)s * f0, &s0, &c0);
        sincosf((float)s * f1, &s1, &c1);

        float o0 = a0 * c0 - a1 * s0, o1 = a1 * c0 + a0 * s0;
        float o2 = a2 * c1 - a3 * s1, o3 = a3 * c1 + a2 * s1;

        *(unsigned*)&dsth[dst + i0] = pack2h(o0, o1);
        *(unsigned*)&dsth[dst + i1] = pack2h(o2, o3);
    } else {
        const __half* p = qkv + (size_t)row * NQKV + 2560 + (slot - 20) * 96;
        size_t dst = ((size_t)row * HKV_ + (slot - 20)) * 96;
        float x0 = __half2float(p[lane]);
        float x1 = __half2float(p[lane + 32]);
        float x2 = __half2float(p[lane + 64]);
        float sum = x0 + x1 + x2;
        #pragma unroll
        for (int o = 16; o > 0; o >>= 1) sum += __shfl_xor_sync(0xffffffffu, sum, o);
        float mu = sum * (1.f / 96.f);
        float d0 = x0 - mu, d1 = x1 - mu, d2 = x2 - mu;
        float sq = d0 * d0 + d1 * d1 + d2 * d2;
        #pragma unroll
        for (int o = 16; o > 0; o >>= 1) sq += __shfl_xor_sync(0xffffffffu, sq, o);
        float inv = rsqrtf(sq * (1.f / 96.f) + EPS_);
        g_vh[dst + lane]      = __float2half_rn(d0 * inv * vn_g[lane]      + vn_b[lane]);
        g_vh[dst + lane + 32] = __float2half_rn(d1 * inv * vn_g[lane + 32] + vn_b[lane + 32]);
        g_vh[dst + lane + 64] = __float2half_rn(d2 * inv * vn_g[lane + 64] + vn_b[lane + 64]);
    }
}

// ==================== mma.sync fp16 attention, split-kv x2, 2 CTAs/SM ====================
#define Q_BYTES    32768
#define K_BYTES    16384
#define V_STRIDE   208
#define V_BYTES    (64 * V_STRIDE)
#define KV_BUF     (K_BYTES + V_BYTES)          // 29696
#define ATT_SMEM   (Q_BYTES + 2 * KV_BUF)       // 92160; x2 CTAs = 184320 < 228KB/SM

__global__ __launch_bounds__(256, 2)
void attn_mma_kernel() {
    extern __shared__ __align__(1024) char sm[];
    const unsigned sb = smem_u32(sm);
    const int qb  = blockIdx.x;
    const int h   = blockIdx.y;
    const int bb  = blockIdx.z >> 1;
    const int kvs = blockIdx.z & 1;
    const int hk = h & (HKV_ - 1);
    const int tid = threadIdx.x, wid = tid >> 5, lane = tid & 31;

    {   // Q loads (grouped with kv tile 0)
        #pragma unroll
        for (int it = 0; it < 8; it++) {
            int chunk = it * 256 + tid;
            int row = chunk >> 4, c = chunk & 15;
            unsigned off = row * 256 + c * 16;
            off ^= (off >> 4) & 0x70;
            const __half* src = g_qh +
                ((size_t)(bb * S_ + qb * 128 + row) * HQ_ + h) * DQK_ + c * 8;
            CPASYNC16(sb + off, (const void*)src);
        }
    }

    auto load_kv = [&](int kt, int buf) {
        unsigned base = sb + Q_BYTES + buf * KV_BUF;
        int s0 = (kvs * 16 + kt) * 64;
        #pragma unroll
        for (int it = 0; it < 4; it++) {
            int chunk = it * 256 + tid;
            int row = chunk >> 4, c = chunk & 15;
            unsigned off = row * 256 + c * 16;
            off ^= (off >> 4) & 0x70;
            const __half* src = g_kh +
                ((size_t)(bb * S_ + s0 + row) * HKV_ + hk) * DQK_ + c * 8;
            CPASYNC16(base + off, (const void*)src);
        }
        #pragma unroll
        for (int it = 0; it < 3; it++) {
            int chunk = it * 256 + tid;
            int row = chunk / 12, c = chunk % 12;
            unsigned off = row * V_STRIDE + c * 16;
            const __half* src = g_vh +
                ((size_t)(bb * S_ + s0 + row) * HKV_ + hk) * DV_ + c * 8;
            CPASYNC16(base + K_BYTES + off, (const void*)src);
        }
        CPASYNC_COMMIT();
    };

    load_kv(0, 0);

    float o_[12][4];
    #pragma unroll
    for (int t = 0; t < 12; t++)
        #pragma unroll
        for (int q = 0; q < 4; q++) o_[t][q] = 0.f;
    float rs0 = 0.f, rs1 = 0.f;

    const float scale = 0.08838834764831845f;
    const int a_row  = wid * 16 + (lane & 15);
    const unsigned a_byte = (lane >> 4) << 4;
    const int b_rowc = (lane & 7) + ((lane >> 4) << 3);
    const unsigned b_byte = ((lane >> 3) & 1) << 4;
    const unsigned voff = (unsigned)(lane & 15) * V_STRIDE + ((lane >> 4) << 4);

    const int NT = 16;
    for (int kb = 0; kb < NT; kb++) {
        int b = kb & 1;
        CPASYNC_WAIT0();
        __syncthreads();
        if (kb + 1 < NT) load_kv(kb + 1, b ^ 1);

        unsigned baseK = sb + Q_BYTES + b * KV_BUF;
        unsigned baseV = baseK + K_BYTES;

        float sc[8][4];
        #pragma unroll
        for (int t = 0; t < 8; t++)
            #pragma unroll
            for (int q = 0; q < 4; q++) sc[t][q] = 0.f;

        #pragma unroll
        for (int ks = 0; ks < 8; ks++) {
            unsigned offA = (unsigned)a_row * 256 + a_byte + ks * 32;
            offA ^= (offA >> 4) & 0x70;
            unsigned qh0, qh1, qh2, qh3;
            LDSM4(qh0, qh1, qh2, qh3, sb + offA);
            #pragma unroll
            for (int p = 0; p < 4; p++) {
                unsigned offB = (unsigned)(p * 16 + b_rowc) * 256 + b_byte + ks * 32;
                offB ^= (offB >> 4) & 0x70;
                unsigned kh0, kh1, kh2, kh3;
                LDSM4(kh0, kh1, kh2, kh3, baseK + offB);
                MMA16816(sc[2*p],   qh0, qh1, qh2, qh3, kh0, kh1);
                MMA16816(sc[2*p+1], qh0, qh1, qh2, qh3, kh2, kh3);
            }
        }

        // softcap one j-group; interleave MUFU with PV tensor work
        unsigned ah[4][4];
        auto docap = [&](int j) {
            #pragma unroll
            for (int tt = 0; tt < 2; tt++) {
                int t = 2 * j + tt;
                #pragma unroll
                for (int q = 0; q < 4; q++) {
                    float l = sc[t][q] * scale;
                    float e = __expf(0.4f * l);
                    float th = 1.f - __fdividef(2.f, e + 1.f);
                    float pp = __expf(CLIP_ * th);
                    sc[t][q] = pp;
                    if (q < 2) rs0 += pp; else rs1 += pp;
                }
            }
            ah[j][0] = pack2h(sc[2*j][0],   sc[2*j][1]);
            ah[j][1] = pack2h(sc[2*j][2],   sc[2*j][3]);
            ah[j][2] = pack2h(sc[2*j+1][0], sc[2*j+1][1]);
            ah[j][3] = pack2h(sc[2*j+1][2], sc[2*j+1][3]);
        };

        docap(0);
        #pragma unroll
        for (int j = 0; j < 4; j++) {
            #pragma unroll
            for (int ct = 0; ct < 3; ct++) {
                #pragma unroll
                for (int half = 0; half < 2; half++) {
                    unsigned a0 = voff + j * (16 * V_STRIDE) + ct * 64 + half * 32;
                    unsigned vh0, vh1, vh2, vh3;
                    LDSM4T(vh0, vh1, vh2, vh3, baseV + a0);
                    int nt = ct * 4 + half * 2;
                    MMA16816(o_[nt],   ah[j][0], ah[j][1], ah[j][2], ah[j][3], vh0, vh1);
                    MMA16816(o_[nt+1], ah[j][0], ah[j][1], ah[j][2], ah[j][3], vh2, vh3);
                }
            }
            if (j < 3) docap(j + 1);
        }
    }

    rs0 += __shfl_xor_sync(0xffffffffu, rs0, 1);
    rs0 += __shfl_xor_sync(0xffffffffu, rs0, 2);
    rs1 += __shfl_xor_sync(0xffffffffu, rs1, 1);
    rs1 += __shfl_xor_sync(0xffffffffu, rs1, 2);

    int r0 = qb * 128 + wid * 16 + (lane >> 2);
    size_t base0 = (((size_t)kvs * M_ + bb * S_ + r0) * HQ_ + h) * DV_;
    size_t base1 = base0 + 8 * (size_t)(HQ_ * DV_);
    #pragma unroll
    for (int nt = 0; nt < 12; nt++) {
        int c = nt * 8 + (lane & 3) * 2;
        float2 v0; v0.x = o_[nt][0]; v0.y = o_[nt][1];
        float2 v1; v1.x = o_[nt][2]; v1.y = o_[nt][3];
        *(float2*)&g_part[base0 + c] = v0;
        *(float2*)&g_part[base1 + c] = v1;
    }
    if ((lane & 3) == 0) {
        g_psum[((size_t)kvs * M_ + bb * S_ + r0) * HQ_ + h]       = rs0;
        g_psum[((size_t)kvs * M_ + bb * S_ + r0 + 8) * HQ_ + h]   = rs1;
    }
}

// ---------------- combine split-kv partials -> single fp16 y ----------------
__global__ void attn_combine_kernel() {
    int idx = blockIdx.x * blockDim.x + threadIdx.x;
    int r   = idx / (HQ_ * 24);
    int rem = idx - r * (HQ_ * 24);
    int h   = rem / 24;
    int c4  = (rem - h * 24) * 4;
    size_t o0 = ((size_t)r * HQ_ + h) * DV_ + c4;
    float4 p0 = *(float4*)&g_part[o0];
    float4 p1 = *(float4*)&g_part[(size_t)M_ * HQ_ * DV_ + o0];
    float s = g_psum[(size_t)r * HQ_ + h] + g_psum[(size_t)M_ * HQ_ + (size_t)r * HQ_ + h];
    float inv = 1.0f / s;
    *(unsigned*)&g_y[o0]     = pack2h((p0.x + p1.x) * inv, (p0.y + p1.y) * inv);
    *(unsigned*)&g_y[o0 + 2] = pack2h((p0.z + p1.z) * inv, (p0.w + p1.w) * inv);
}

// ---------------- launch ----------------
extern "C" void kernel_launch(void* const* d_in, const int* in_sizes, int n_in,
                              void* d_out, int out_size) {
    const float* x      = (const float*)d_in[0];
    const float* bn1_g  = (const float*)d_in[1];
    const float* bn1_ms = (const float*)d_in[2];
    const float* Wq     = (const float*)d_in[3];
    const float* Wk     = (const float*)d_in[4];
    const float* Wv     = (const float*)d_in[5];
    const float* qn_g   = (const float*)d_in[6];
    const float* qn_b   = (const float*)d_in[7];
    const float* kn_g   = (const float*)d_in[8];
    const float* kn_b   = (const float*)d_in[9];
    const float* vn_g   = (const float*)d_in[10];
    const float* vn_b   = (const float*)d_in[11];
    const float* Wo     = (const float*)d_in[12];
    const float* bo     = (const float*)d_in[13];
    const float* bn2_g  = (const float*)d_in[14];
    const float* bn2_ms = (const float*)d_in[15];
    float* out = (float*)d_out;

    __half *pqkvh, *phh, *pwt, *pwo, *py;
    cudaGetSymbolAddress((void**)&pqkvh, g_qkvh);
    cudaGetSymbolAddress((void**)&phh, g_hh);
    cudaGetSymbolAddress((void**)&pwt, g_wt);
    cudaGetSymbolAddress((void**)&pwo, g_wo);
    cudaGetSymbolAddress((void**)&py, g_y);

    cudaFuncSetAttribute((const void*)mma_gemm_kernel<128, true>,
                         cudaFuncAttributeMaxDynamicSharedMemorySize, 4 * 32768);
    cudaFuncSetAttribute((const void*)mma_gemm_kernel<64, false>,
                         cudaFuncAttributeMaxDynamicSharedMemorySize, 4 * 24576);
    cudaFuncSetAttribute(attn_mma_kernel, cudaFuncAttributeMaxDynamicSharedMemorySize, ATT_SMEM);

    // 1. x -> fp16 (bn1 folded into weights)
    cvt_kernel<<<(M_ * C_ / 4) / 256, 256>>>(x, phh);
    // 2. Wo transpose
    transpose_h_kernel<<<dim3(C_/32, C_/32), dim3(32,8)>>>(Wo, pwo, C_, C_);
    // 3. packed QKV weight transpose with bn1 scale
    transpose_qkv_kernel<<<dim3(NQKV/32, C_/32), dim3(32,8)>>>(Wq, Wk, Wv, bn1_g, bn1_ms, pwt);
    // 4. merged QKV projection, 256 threads, fp16 out (profiled launch)
    mma_gemm_kernel<128, true><<<dim3(NQKV/128, M_/128), 256, 4 * 32768>>>(
        phh, pwt, pqkvh, M_, NQKV, C_, nullptr, nullptr, nullptr);
    // 5. merged LN (+RoPE), fp16 in
    ln_all_kernel<<<(M_ * 24) / 8, 256>>>(pqkvh, qn_g, qn_b, kn_g, kn_b, vn_g, vn_b);
    // 6. attention, split-kv x2, 2 CTAs/SM
    attn_mma_kernel<<<dim3(S_ / 128, HQ_, B_ * 2), 256, ATT_SMEM>>>();
    // 7. combine partials -> y fp16
    attn_combine_kernel<<<(M_ * HQ_ * 24) / 256, 256>>>();
    // 8. out projection + bias + rms_bn2 -> d_out
    mma_gemm_kernel<64, false><<<dim3(C_/64, M_/128), 256, 4 * 24576>>>(
        py, pwo, out, M_, C_, HQ_*DV_, bo, bn2_g, bn2_ms);
}